// round 14
// baseline (speedup 1.0000x reference)
#include <cuda_runtime.h>
#include <math.h>
#include <stdint.h>

#define BATCH 8
#define KNNK 20
#define N1 4096
#define N2 1024
#define N3 256

// ======================= device scratch =======================
__device__ float g_fo[BATCH * 4096 * 128];
__device__ float g_fa[BATCH * 4096 * 64];
__device__ float g_fb[BATCH * 4096 * 64];
__device__ int   g_nb[BATCH * 4096 * KNNK];
__device__ float g_ndirs[1504 * 3];
__device__ int   g_pool1[1024];
__device__ int   g_pool2[256];
__device__ float g_act[BATCH * 256 * 64];
__device__ float g_bnm[64];
__device__ float g_bnv[64];
__device__ float g_vlad[BATCH * 1024 * 64];
__device__ float g_cn[BATCH * 64];
__device__ float g_tn[BATCH];
__device__ float g_part[64 * BATCH * 1024];
__device__ float g_v2[BATCH * 1024 * 3];
__device__ float g_v3[BATCH * 256 * 3];

__device__ __forceinline__ void kadd(float& s, float& c, float v) {
    float y = __fadd_rn(v, -c);
    float t = __fadd_rn(s, y);
    c = __fadd_rn(__fadd_rn(t, -s), -y);
    s = t;
}

struct PoolParams { int p1[1024]; int p2[256]; };

// ======================= KNN body (R5/R7 exact form) =======================
#define KNN_TILE 128
__device__ __forceinline__ void knn_core(const float* __restrict__ v, int N,
                                         float4* sp, int* bi_out) {
    int b = blockIdx.y;
    int i = blockIdx.x * blockDim.x + threadIdx.x;
    const float* vb = v + (size_t)b * N * 3;
    float xi = vb[i * 3], yi = vb[i * 3 + 1], zi = vb[i * 3 + 2];
    float sqi = __fadd_rn(__fadd_rn(__fmul_rn(xi, xi), __fmul_rn(yi, yi)), __fmul_rn(zi, zi));

    float bd[KNNK]; int bi_[KNNK];
#pragma unroll
    for (int t = 0; t < KNNK; t++) { bd[t] = INFINITY; bi_[t] = 0x7fffffff; }
    float worst_d = INFINITY; int wslot = 0;

    for (int base = 0; base < N; base += KNN_TILE) {
        {
            int t = threadIdx.x;
            float X = vb[(base + t) * 3], Y = vb[(base + t) * 3 + 1], Z = vb[(base + t) * 3 + 2];
            float S = __fadd_rn(__fadd_rn(__fmul_rn(X, X), __fmul_rn(Y, Y)), __fmul_rn(Z, Z));
            sp[t] = make_float4(X, Y, Z, S);
        }
        __syncthreads();
        for (int t = 0; t < KNN_TILE; t += 4) {
            float d4_[4];
#pragma unroll
            for (int u = 0; u < 4; u++) {
                float4 q = sp[t + u];
                float dot = fmaf(zi, q.z, fmaf(yi, q.y, __fmul_rn(xi, q.x)));
                d4_[u] = __fadd_rn(__fadd_rn(sqi, q.w), -__fmul_rn(2.f, dot));
            }
#pragma unroll
            for (int u = 0; u < 4; u++) {
                int j = base + t + u;
                float d = d4_[u];
                if (j != i && d < worst_d) {
#pragma unroll
                    for (int s = 0; s < KNNK; s++) if (s == wslot) { bd[s] = d; bi_[s] = j; }
                    worst_d = bd[0]; wslot = 0;
#pragma unroll
                    for (int s = 1; s < KNNK; s++) {
                        if (bd[s] > worst_d) { worst_d = bd[s]; wslot = s; }
                    }
                }
            }
        }
        __syncthreads();
    }
#pragma unroll
    for (int t = 0; t < KNNK; t++) bi_out[t] = bi_[t];
}

__global__ void knn_kernel(const float* __restrict__ v, int N, int* __restrict__ nb) {
    __shared__ float4 sp[KNN_TILE];
    int bi_[KNNK];
    knn_core(v, N, sp, bi_);
    int b = blockIdx.y;
    int i = blockIdx.x * blockDim.x + threadIdx.x;
#pragma unroll
    for (int t = 0; t < KNNK; t++) nb[((size_t)b * N + i) * KNNK + t] = bi_[t];
}

// knn stage-1 + pools/ndirs init (block 0) + fused conv_surface (fm written directly)
__global__ void knn_init_surf_kernel(PoolParams pp,
                                     const float* __restrict__ d0, const float* __restrict__ d1,
                                     const float* __restrict__ d2, const float* __restrict__ d3,
                                     const float* __restrict__ d4,
                                     const float* __restrict__ v, int* __restrict__ nb,
                                     float* __restrict__ fm) {
    __shared__ float4 sp[KNN_TILE];
    __shared__ float sd0[32 * 3];
    if (blockIdx.x == 0 && blockIdx.y == 0) {
        for (int t = threadIdx.x; t < 1024; t += 128) g_pool1[t] = pp.p1[t];
        for (int t = threadIdx.x; t < 256;  t += 128) g_pool2[t] = pp.p2[t];
        for (int t = threadIdx.x; t < 1504; t += 128) {
            const float* src; int F, off, f;
            if      (t < 32)  { src = d0; F = 32;   off = 0;   f = t; }
            else if (t < 96)  { src = d1; F = 64;   off = 32;  f = t - 32; }
            else if (t < 224) { src = d2; F = 128;  off = 96;  f = t - 96; }
            else if (t < 480) { src = d3; F = 256;  off = 224; f = t - 224; }
            else              { src = d4; F = 1024; off = 480; f = t - 480; }
            float a = src[f], b = src[F + f], c = src[2 * F + f];
            float n = fmaxf(sqrtf(a * a + b * b + c * c), 1e-12f);
            g_ndirs[(off + f) * 3]     = a / n;
            g_ndirs[(off + f) * 3 + 1] = b / n;
            g_ndirs[(off + f) * 3 + 2] = c / n;
        }
    }
    // local dir0 normalization (identical expression; visible after first knn barrier)
    if (threadIdx.x < 32) {
        int f = threadIdx.x;
        float a = d0[f], b = d0[32 + f], c = d0[64 + f];
        float n = fmaxf(sqrtf(a * a + b * b + c * c), 1e-12f);
        sd0[f * 3] = a / n; sd0[f * 3 + 1] = b / n; sd0[f * 3 + 2] = c / n;
    }
    int bi_[KNNK];
    knn_core(v, N1, sp, bi_);
    int b = blockIdx.y;
    int i = blockIdx.x * blockDim.x + threadIdx.x;
#pragma unroll
    for (int t = 0; t < KNNK; t++) nb[((size_t)b * N1 + i) * KNNK + t] = bi_[t];

    // fused conv_surface: this thread's point, 20 neighbor dirs -> fm (32 features)
    const float* vb = v + (size_t)b * N1 * 3;
    float sdx[KNNK], sdy[KNNK], sdz[KNNK];
#pragma unroll
    for (int k = 0; k < KNNK; k++) {
        int j = bi_[k];
        float dx = vb[j * 3] - vb[i * 3];
        float dy = vb[j * 3 + 1] - vb[i * 3 + 1];
        float dz = vb[j * 3 + 2] - vb[i * 3 + 2];
        float nm = fmaxf(sqrtf(dx * dx + dy * dy + dz * dz), 1e-12f);
        sdx[k] = dx / nm; sdy[k] = dy / nm; sdz[k] = dz / nm;
    }
    float* fmrow = fm + ((size_t)b * N1 + i) * 32;
    for (int f = 0; f < 32; f++) {
        float d0v = sd0[f * 3], d1v = sd0[f * 3 + 1], d2v = sd0[f * 3 + 2];
        float m = 0.f;
#pragma unroll
        for (int k = 0; k < KNNK; k++) {
            float th = fmaxf(sdx[k] * d0v + sdy[k] * d1v + sdz[k] * d2v, 0.f);
            m = fmaxf(m, th);
        }
        fmrow[f] = m;
    }
}

// ======================= conv_layer activation: float4 channels per thread (R12 winner) ==
__global__ void conv_act_kernel(const float* __restrict__ v, const int* __restrict__ nb,
                                const float* __restrict__ ndirs, const float* __restrict__ fo,
                                float* __restrict__ out, int N, int OC, int G, int relu_out) {
    int C = 2 * OC;
    __shared__ float sdx[320], sdy[320], sdz[320];
    __shared__ int sj[320];
    int p0 = blockIdx.x * G;
    int t = threadIdx.x;
    for (int e = t; e < G * KNNK; e += 256) {
        int g = e / KNNK, k = e % KNNK;
        int p = p0 + g; int b = p / N; int n = p % N;
        const float* vb = v + (size_t)b * N * 3;
        int j = nb[(size_t)p * KNNK + k];
        sj[e] = b * N + j;
        float dx = vb[j * 3] - vb[n * 3];
        float dy = vb[j * 3 + 1] - vb[n * 3 + 1];
        float dz = vb[j * 3 + 2] - vb[n * 3 + 2];
        float nm = fmaxf(sqrtf(dx * dx + dy * dy + dz * dz), 1e-12f);
        sdx[e] = dx / nm; sdy[e] = dy / nm; sdz[e] = dz / nm;
    }
    __syncthreads();
    int TP = 256 / G;
    int g = t / TP, fq = t % TP;
    int p = p0 + g;
    int kb = g * KNNK;
    int OCq = OC / 4;
    const float* forow = fo + (size_t)p * C;
    for (int f4 = fq; f4 < OCq; f4 += TP) {
        int f = f4 * 4;
        float4 dA = *(const float4*)&ndirs[f * 3];
        float4 dB = *(const float4*)&ndirs[f * 3 + 4];
        float4 dC = *(const float4*)&ndirs[f * 3 + 8];
        float m0 = -INFINITY, m1 = -INFINITY, m2 = -INFINITY, m3 = -INFINITY;
#pragma unroll
        for (int k = 0; k < KNNK; k++) {
            float sx = sdx[kb + k], sy = sdy[kb + k], sz = sdz[kb + k];
            float4 fs = *(const float4*)&fo[(size_t)sj[kb + k] * C + OC + f];
            float th0 = fmaxf(sx * dA.x + sy * dA.y + sz * dA.z, 0.f);
            float th1 = fmaxf(sx * dA.w + sy * dB.x + sz * dB.y, 0.f);
            float th2 = fmaxf(sx * dB.z + sy * dB.w + sz * dC.x, 0.f);
            float th3 = fmaxf(sx * dC.y + sy * dC.z + sz * dC.w, 0.f);
            m0 = fmaxf(m0, th0 * fs.x);
            m1 = fmaxf(m1, th1 * fs.y);
            m2 = fmaxf(m2, th2 * fs.z);
            m3 = fmaxf(m3, th3 * fs.w);
        }
        float4 fr = *(const float4*)&forow[f];
        float4 val = make_float4(fr.x + m0, fr.y + m1, fr.z + m2, fr.w + m3);
        if (relu_out) {
            val.x = fmaxf(val.x, 0.f); val.y = fmaxf(val.y, 0.f);
            val.z = fmaxf(val.z, 0.f); val.w = fmaxf(val.w, 0.f);
        }
        *(float4*)&out[(size_t)p * OC + f] = val;
    }
}

// ======================= fused gather_max + pool + coord gather =======================
__global__ void gather_max_pool_kernel(const float* __restrict__ fm, const int* __restrict__ nb,
                                       const int* __restrict__ pool, const float* __restrict__ vin,
                                       float* __restrict__ out, float* __restrict__ vout,
                                       int Nin, int Nout, int F) {
    int F4 = F / 4;
    int idx = blockIdx.x * blockDim.x + threadIdx.x;
    int tot = BATCH * Nout * F4;
    if (idx < tot) {
        int f4 = idx % F4; int r = idx / F4; int b = r / Nout; int pp = r % Nout;
        int row = pool[pp];
        const int* nbp = nb + ((size_t)b * Nin + row) * KNNK;
        float4 m = make_float4(-INFINITY, -INFINITY, -INFINITY, -INFINITY);
#pragma unroll
        for (int k = 0; k < KNNK; k++) {
            const float4 vv = *(const float4*)&fm[((size_t)b * Nin + nbp[k]) * F + f4 * 4];
            m.x = fmaxf(m.x, vv.x); m.y = fmaxf(m.y, vv.y);
            m.z = fmaxf(m.z, vv.z); m.w = fmaxf(m.w, vv.w);
        }
        *(float4*)&out[(size_t)r * F + f4 * 4] = m;
    }
    if (idx < BATCH * Nout * 3) {
        int f = idx % 3; int r = idx / 3; int b = r / Nout; int pp = r % Nout;
        vout[idx] = vin[((size_t)b * Nin + pool[pp]) * 3 + f];
    }
}

// ======================= 128x128 SGEMM (R12 winner form) =======================
#define GT 132
__global__ __launch_bounds__(256, 2) void gemm128_kernel(
        const float* __restrict__ A, const float* __restrict__ B,
        const float* __restrict__ bias, float* __restrict__ C,
        int M, int K, int N) {
    __shared__ float As[8][GT];
    __shared__ float Bs[8][GT];
    int row0 = blockIdx.y * 128, col0 = blockIdx.x * 128;
    int tid = threadIdx.x;
    int tx = tid % 16, ty = tid / 16;
    int arow = tid >> 1, acol = (tid & 1) * 4;
    int brow = tid >> 5, bcol = (tid & 31) * 4;
    float4 pa = *(const float4*)&A[(size_t)(row0 + arow) * K + acol];
    float4 pb = *(const float4*)&B[(size_t)brow * N + col0 + bcol];
    float acc[8][8] = {};
    for (int k0 = 0; k0 < K; k0 += 8) {
        As[acol][arow] = pa.x; As[acol + 1][arow] = pa.y;
        As[acol + 2][arow] = pa.z; As[acol + 3][arow] = pa.w;
        *(float4*)&Bs[brow][bcol] = pb;
        __syncthreads();
        if (k0 + 8 < K) {
            pa = *(const float4*)&A[(size_t)(row0 + arow) * K + k0 + 8 + acol];
            pb = *(const float4*)&B[(size_t)(k0 + 8 + brow) * N + col0 + bcol];
        }
#pragma unroll
        for (int kk = 0; kk < 8; kk++) {
            float a[8], bb[8];
            *(float4*)&a[0] = *(const float4*)&As[kk][ty * 8];
            *(float4*)&a[4] = *(const float4*)&As[kk][ty * 8 + 4];
            *(float4*)&bb[0] = *(const float4*)&Bs[kk][tx * 8];
            *(float4*)&bb[4] = *(const float4*)&Bs[kk][tx * 8 + 4];
#pragma unroll
            for (int i = 0; i < 8; i++)
#pragma unroll
                for (int j = 0; j < 8; j++) acc[i][j] = fmaf(a[i], bb[j], acc[i][j]);
        }
        __syncthreads();
    }
    float bz[8];
    if (bias) {
        *(float4*)&bz[0] = *(const float4*)&bias[col0 + tx * 8];
        *(float4*)&bz[4] = *(const float4*)&bias[col0 + tx * 8 + 4];
    } else {
#pragma unroll
        for (int j = 0; j < 8; j++) bz[j] = 0.f;
    }
#pragma unroll
    for (int i = 0; i < 8; i++) {
        float* crow = &C[(size_t)(row0 + ty * 8 + i) * N + col0 + tx * 8];
        float4 r0 = make_float4(acc[i][0] + bz[0], acc[i][1] + bz[1], acc[i][2] + bz[2], acc[i][3] + bz[3]);
        float4 r1 = make_float4(acc[i][4] + bz[4], acc[i][5] + bz[5], acc[i][6] + bz[6], acc[i][7] + bz[7]);
        *(float4*)crow = r0;
        *(float4*)(crow + 4) = r1;
    }
}

// ======================= cluster GEMM: 32x64 tiles, tile-compensated =======================
__global__ void gemm_kahan_kernel(const float* __restrict__ A, const float* __restrict__ B,
                                  float* __restrict__ C, int M, int K, int N) {
    __shared__ float As[16][36];
    __shared__ float Bs[16][68];
    int row0 = blockIdx.y * 32;
    int tid = threadIdx.x;
    int tx = tid % 16, ty = tid / 16;
    float acc[2][4] = {}; float cmp[2][4] = {};
    int ar = tid >> 2, ac4 = (tid & 3) * 4;
    int br = tid >> 4, bc4 = (tid & 15) * 4;
    for (int k0 = 0; k0 < K; k0 += 16) {
        if (tid < 128) {
            float4 av = *(const float4*)&A[(size_t)(row0 + ar) * K + k0 + ac4];
            As[ac4][ar] = av.x; As[ac4 + 1][ar] = av.y; As[ac4 + 2][ar] = av.z; As[ac4 + 3][ar] = av.w;
        }
        *(float4*)&Bs[br][bc4] = *(const float4*)&B[(size_t)(k0 + br) * N + bc4];
        __syncthreads();
        float tacc[2][4] = {};
#pragma unroll
        for (int kk = 0; kk < 16; kk++) {
            float a[2], bb[4];
            a[0] = As[kk][ty * 2]; a[1] = As[kk][ty * 2 + 1];
            float4 b4 = *(const float4*)&Bs[kk][tx * 4];
            bb[0] = b4.x; bb[1] = b4.y; bb[2] = b4.z; bb[3] = b4.w;
#pragma unroll
            for (int i = 0; i < 2; i++)
#pragma unroll
                for (int j = 0; j < 4; j++) tacc[i][j] = fmaf(a[i], bb[j], tacc[i][j]);
        }
#pragma unroll
        for (int i = 0; i < 2; i++)
#pragma unroll
            for (int j = 0; j < 4; j++) kadd(acc[i][j], cmp[i][j], tacc[i][j]);
        __syncthreads();
    }
#pragma unroll
    for (int i = 0; i < 2; i++)
#pragma unroll
        for (int j = 0; j < 4; j++)
            C[(size_t)(row0 + ty * 2 + i) * N + tx * 4 + j] = acc[i][j];
}

// ======================= GeM =======================
__device__ __forceinline__ float fast_pow(float x, float p) {
    return exp2f(p * log2f(x));
}
__global__ void gem_kernel(const float* __restrict__ fm4, const float* __restrict__ gem_p,
                           float* __restrict__ y) {
    int b = blockIdx.x;
    int c4 = threadIdx.x * 4;
    float p = gem_p[0];
    bool p3 = (p == 3.0f);
    float s[4] = {}; float sc[4] = {};
    for (int nc = 0; nc < 8; nc++) {
        float t[4] = {};
        for (int n = nc * 32; n < nc * 32 + 32; n++) {
            float4 f = *(const float4*)&fm4[((size_t)b * N3 + n) * 1024 + c4];
            float fx = fmaxf(f.x, 1e-6f), fy = fmaxf(f.y, 1e-6f);
            float fz = fmaxf(f.z, 1e-6f), fw = fmaxf(f.w, 1e-6f);
            if (p3) {
                t[0] = __fadd_rn(t[0], fx * fx * fx);
                t[1] = __fadd_rn(t[1], fy * fy * fy);
                t[2] = __fadd_rn(t[2], fz * fz * fz);
                t[3] = __fadd_rn(t[3], fw * fw * fw);
            } else {
                t[0] = __fadd_rn(t[0], fast_pow(fx, p));
                t[1] = __fadd_rn(t[1], fast_pow(fy, p));
                t[2] = __fadd_rn(t[2], fast_pow(fz, p));
                t[3] = __fadd_rn(t[3], fast_pow(fw, p));
            }
        }
#pragma unroll
        for (int u = 0; u < 4; u++) kadd(s[u], sc[u], t[u]);
    }
    float4 r;
    if (p3) {
        r.x = cbrtf(s[0] / (float)N3); r.y = cbrtf(s[1] / (float)N3);
        r.z = cbrtf(s[2] / (float)N3); r.w = cbrtf(s[3] / (float)N3);
    } else {
        float ip = 1.f / p;
        r.x = fast_pow(s[0] / (float)N3, ip); r.y = fast_pow(s[1] / (float)N3, ip);
        r.z = fast_pow(s[2] / (float)N3, ip); r.w = fast_pow(s[3] / (float)N3, ip);
    }
    *(float4*)&y[b * 1024 + c4] = r;
}

// ======================= NetVLAD =======================
__global__ void bn1_stats_kernel(const float* __restrict__ act, float* __restrict__ mean,
                                 float* __restrict__ var, int rows) {
    int k = blockIdx.x;
    __shared__ double sd[256];
    float a = 0.f, ac = 0.f;
    for (int r = threadIdx.x; r < rows; r += 256) kadd(a, ac, act[(size_t)r * 64 + k]);
    sd[threadIdx.x] = (double)a; __syncthreads();
    for (int s = 128; s > 0; s >>= 1) {
        if (threadIdx.x < s) sd[threadIdx.x] += sd[threadIdx.x + s];
        __syncthreads();
    }
    float m = (float)(sd[0] / rows);
    __syncthreads();
    float q = 0.f, qc = 0.f;
    for (int r = threadIdx.x; r < rows; r += 256) {
        float d = __fadd_rn(act[(size_t)r * 64 + k], -m);
        kadd(q, qc, __fmul_rn(d, d));
    }
    sd[threadIdx.x] = (double)q; __syncthreads();
    for (int s = 128; s > 0; s >>= 1) {
        if (threadIdx.x < s) sd[threadIdx.x] += sd[threadIdx.x + s];
        __syncthreads();
    }
    if (threadIdx.x == 0) { mean[k] = m; var[k] = (float)(sd[0] / rows); }
}

__global__ void bn_softmax_kernel(float* __restrict__ act, const float* __restrict__ mean,
                                  const float* __restrict__ var, const float* __restrict__ g,
                                  const float* __restrict__ bb) {
    int r = blockIdx.x * 4 + threadIdx.x / 64;
    int k = threadIdx.x % 64;
    int rb = (threadIdx.x / 64) * 64;
    __shared__ float sv[256];
    float v = (act[(size_t)r * 64 + k] - mean[k]) * rsqrtf(var[k] + 1e-5f) * g[k] + bb[k];
    sv[threadIdx.x] = v; __syncthreads();
    float mx = -INFINITY;
    for (int t = 0; t < 64; t++) mx = fmaxf(mx, sv[rb + t]);
    float e = expf(v - mx);
    __syncthreads(); sv[threadIdx.x] = e; __syncthreads();
    float s = 0.f, sc = 0.f;
    for (int t = 0; t < 64; t++) kadd(s, sc, sv[rb + t]);
    act[(size_t)r * 64 + k] = e / s;
}

// vlad with asum computed in-block
__global__ void vlad_kernel(const float* __restrict__ act, const float* __restrict__ xv,
                            const float* __restrict__ cw2, float* __restrict__ vlad) {
    int b = blockIdx.y;
    int k = threadIdx.x % 64;
    int fi = threadIdx.x / 64;
    int f = blockIdx.x * 4 + fi;
    __shared__ float sasum[64];
    float s = 0.f, sc = 0.f;
    for (int m0 = 0; m0 < N3; m0 += 32) {
        float bs = 0.f;
#pragma unroll 8
        for (int m = m0; m < m0 + 32; m++) {
            bs = fmaf(act[((size_t)b * N3 + m) * 64 + k], xv[((size_t)b * N3 + m) * 1024 + f], bs);
        }
        kadd(s, sc, bs);
    }
    if (fi == 0) {
        float sa = 0.f, sac = 0.f;
        for (int m0 = 0; m0 < N3; m0 += 32) {
            float bsa = 0.f;
#pragma unroll 8
            for (int m = m0; m < m0 + 32; m++) bsa = __fadd_rn(bsa, act[((size_t)b * N3 + m) * 64 + k]);
            kadd(sa, sac, bsa);
        }
        sasum[k] = sa;
    }
    __syncthreads();
    s = __fadd_rn(s, -__fmul_rn(sasum[k], cw2[(size_t)f * 64 + k]));
    vlad[((size_t)b * 1024 + f) * 64 + k] = s;
}

// colnorm + tn fused
__global__ void colnorm_tn_kernel(const float* __restrict__ vlad, float* __restrict__ cn,
                                  float* __restrict__ tn) {
    int b = blockIdx.x; int tid = threadIdx.x;
    int k = tid % 64, grp = tid / 64;
    float s = 0.f, sc = 0.f;
    for (int q0 = 0; q0 < 64; q0 += 16) {
        float bs = 0.f;
#pragma unroll
        for (int q = q0; q < q0 + 16; q++) {
            int f = grp + q * 16;
            float v = vlad[((size_t)b * 1024 + f) * 64 + k];
            bs = fmaf(v, v, bs);
        }
        kadd(s, sc, bs);
    }
    __shared__ double sm[1024];
    __shared__ float scn[64];
    sm[tid] = (double)s; __syncthreads();
    if (grp == 0) {
        double t = 0.0;
        for (int g2 = 0; g2 < 16; g2++) t += sm[g2 * 64 + k];
        float cv = (float)t;
        cn[b * 64 + k] = cv;
        scn[k] = cv;
    }
    __syncthreads();
    if (tid == 0) {
        double t = 0.0;
        for (int k2 = 0; k2 < 64; k2++) {
            float c = scn[k2];
            float d = fmaxf(sqrtf(c), 1e-12f);
            t += (double)(c / (d * d));
        }
        tn[b] = (float)t;
    }
}

// hidden skinny GEMM with fused vlad normalization on smem load
#define SKC 1024
__global__ void skinny8_norm_kernel(const float* __restrict__ A, const float* __restrict__ W,
                                    const float* __restrict__ cn, const float* __restrict__ tn,
                                    float* __restrict__ part, int K, int N) {
    int j = blockIdx.x * 256 + threadIdx.x;
    int k0 = blockIdx.y * SKC;
    __shared__ float xs[BATCH * SKC];
    __shared__ float s1[BATCH * 64];
    __shared__ float s2[BATCH];
    if (threadIdx.x < 8) s2[threadIdx.x] = 1.f / fmaxf(sqrtf(tn[threadIdx.x]), 1e-12f);
    for (int t = threadIdx.x; t < BATCH * 64; t += 256)
        s1[t] = 1.f / fmaxf(sqrtf(cn[t]), 1e-12f);
    __syncthreads();
    for (int t = threadIdx.x; t < BATCH * SKC; t += 256) {
        int bb = t / SKC; int ii = t % SKC;
        int gi = k0 + ii; int k = gi & 63;
        xs[t] = A[(size_t)bb * K + gi] * s1[bb * 64 + k] * s2[bb];
    }
    __syncthreads();
    if (j < N) {
        float acc[BATCH] = {}; float cmp[BATCH] = {};
#pragma unroll 1
        for (int i0 = 0; i0 < SKC; i0 += 16) {
            float ba[BATCH] = {};
#pragma unroll 8
            for (int i = i0; i < i0 + 16; i++) {
                float w = W[(size_t)(k0 + i) * N + j];
#pragma unroll
                for (int bb = 0; bb < BATCH; bb++) ba[bb] = fmaf(xs[bb * SKC + i], w, ba[bb]);
            }
#pragma unroll
            for (int bb = 0; bb < BATCH; bb++) kadd(acc[bb], cmp[bb], ba[bb]);
        }
#pragma unroll
        for (int bb = 0; bb < BATCH; bb++) {
            part[(size_t)blockIdx.y * BATCH * N + bb * N + j] = acc[bb];
        }
    }
}

// gating skinny GEMM with fused bn2-from-partials + gate BN + sigmoid + multiply
__global__ void skinny8_gate_kernel(const float* __restrict__ part,
                                    const float* __restrict__ bn2_g, const float* __restrict__ bn2_b,
                                    const float* __restrict__ W,
                                    const float* __restrict__ gg, const float* __restrict__ gb,
                                    float* __restrict__ desc) {
    int j = blockIdx.x * 256 + threadIdx.x;
    __shared__ float xs[BATCH * 1024];
    for (int i = 0; i < 4; i++) {
        int jj = threadIdx.x + i * 256;
        float h[BATCH];
#pragma unroll
        for (int b = 0; b < BATCH; b++) {
            float s = 0.f, sc = 0.f;
            for (int c = 0; c < 64; c++) kadd(s, sc, part[(size_t)c * BATCH * 1024 + b * 1024 + jj]);
            h[b] = s;
        }
        double m = 0.0;
#pragma unroll
        for (int b = 0; b < BATCH; b++) m += (double)h[b];
        m /= BATCH;
        double q = 0.0;
#pragma unroll
        for (int b = 0; b < BATCH; b++) { double d = (double)h[b] - m; q += d * d; }
        q /= BATCH;
        float mf = (float)m;
        float inv = rsqrtf((float)q + 1e-5f);
#pragma unroll
        for (int b = 0; b < BATCH; b++)
            xs[b * 1024 + jj] = (h[b] - mf) * inv * bn2_g[jj] + bn2_b[jj];
    }
    __syncthreads();
    float acc[BATCH] = {}; float cmp[BATCH] = {};
#pragma unroll 1
    for (int i0 = 0; i0 < 1024; i0 += 16) {
        float ba[BATCH] = {};
#pragma unroll 4
        for (int i = i0; i < i0 + 16; i++) {
            float w = W[(size_t)i * 1024 + j];
#pragma unroll
            for (int bb = 0; bb < BATCH; bb++) ba[bb] = fmaf(xs[bb * 1024 + i], w, ba[bb]);
        }
#pragma unroll
        for (int bb = 0; bb < BATCH; bb++) kadd(acc[bb], cmp[bb], ba[bb]);
    }
    double m = 0.0;
#pragma unroll
    for (int bb = 0; bb < BATCH; bb++) m += (double)acc[bb];
    m /= BATCH;
    double q = 0.0;
#pragma unroll
    for (int bb = 0; bb < BATCH; bb++) { double d = (double)acc[bb] - m; q += d * d; }
    q /= BATCH;
    float mf = (float)m;
    float inv = rsqrtf((float)q + 1e-5f);
#pragma unroll
    for (int bb = 0; bb < BATCH; bb++) {
        float z = (acc[bb] - mf) * inv * gg[j] + gb[j];
        float s = 1.f / (1.f + expf(-z));
        desc[bb * 1024 + j] = xs[bb * 1024 + j] * s;
    }
}

// ======================= host: numpy-compatible MT19937 pools =======================
struct MTState { uint32_t mt[624]; int idx; };

static void mt_seed(MTState& s, uint32_t seed) {
    for (int p = 0; p < 624; p++) {
        s.mt[p] = seed;
        seed = 1812433253u * (seed ^ (seed >> 30)) + (uint32_t)p + 1u;
    }
    s.idx = 624;
}
static uint32_t mt_next(MTState& s) {
    if (s.idx >= 624) {
        for (int i = 0; i < 624; i++) {
            uint32_t y = (s.mt[i] & 0x80000000u) | (s.mt[(i + 1) % 624] & 0x7fffffffu);
            uint32_t v = s.mt[(i + 397) % 624] ^ (y >> 1);
            if (y & 1u) v ^= 0x9908b0dfu;
            s.mt[i] = v;
        }
        s.idx = 0;
    }
    uint32_t y = s.mt[s.idx++];
    y ^= y >> 11;
    y ^= (y << 7) & 0x9d2c5680u;
    y ^= (y << 15) & 0xefc60000u;
    y ^= y >> 18;
    return y;
}
static uint32_t rk_interval(MTState& s, uint32_t mx) {
    if (mx == 0) return 0;
    uint32_t mask = mx;
    mask |= mask >> 1; mask |= mask >> 2; mask |= mask >> 4;
    mask |= mask >> 8; mask |= mask >> 16;
    uint32_t v;
    while ((v = (mt_next(s) & mask)) > mx) {}
    return v;
}
static void np_permutation(uint32_t seed, int n, int* out) {
    for (int i = 0; i < n; i++) out[i] = i;
    MTState s; mt_seed(s, seed);
    for (int i = n - 1; i >= 1; i--) {
        uint32_t j = rk_interval(s, (uint32_t)i);
        int t = out[i]; out[i] = out[(int)j]; out[(int)j] = t;
    }
}

// ======================= launch =======================
extern "C" void kernel_launch(void* const* d_in, const int* in_sizes, int n_in,
                              void* d_out, int out_size) {
    const float* x         = (const float*)d_in[0];
    const float* dir0      = (const float*)d_in[1];
    const float* W1        = (const float*)d_in[2];
    const float* b1        = (const float*)d_in[3];
    const float* dir1      = (const float*)d_in[4];
    const float* W2        = (const float*)d_in[5];
    const float* b2        = (const float*)d_in[6];
    const float* dir2      = (const float*)d_in[7];
    const float* W3        = (const float*)d_in[8];
    const float* b3        = (const float*)d_in[9];
    const float* dir3      = (const float*)d_in[10];
    const float* W4        = (const float*)d_in[11];
    const float* b4        = (const float*)d_in[12];
    const float* dir4      = (const float*)d_in[13];
    const float* gem_p     = (const float*)d_in[14];
    const float* cluster_w = (const float*)d_in[15];
    const float* cluster_w2= (const float*)d_in[16];
    const float* hidden_w  = (const float*)d_in[17];
    const float* bn1_g     = (const float*)d_in[18];
    const float* bn1_b     = (const float*)d_in[19];
    const float* bn2_g     = (const float*)d_in[20];
    const float* bn2_b     = (const float*)d_in[21];
    const float* gating_w  = (const float*)d_in[22];
    const float* gbn_g     = (const float*)d_in[23];
    const float* gbn_b     = (const float*)d_in[24];
    float* out = (float*)d_out;

    float *fo, *fa, *fb, *ndirs, *v2, *v3, *act, *bnm, *bnv, *vlad, *cn, *tn, *part;
    int *nb, *pool1, *pool2;
    cudaGetSymbolAddress((void**)&fo, g_fo);
    cudaGetSymbolAddress((void**)&fa, g_fa);
    cudaGetSymbolAddress((void**)&fb, g_fb);
    cudaGetSymbolAddress((void**)&nb, g_nb);
    cudaGetSymbolAddress((void**)&ndirs, g_ndirs);
    cudaGetSymbolAddress((void**)&pool1, g_pool1);
    cudaGetSymbolAddress((void**)&pool2, g_pool2);
    cudaGetSymbolAddress((void**)&v2, g_v2);
    cudaGetSymbolAddress((void**)&v3, g_v3);
    cudaGetSymbolAddress((void**)&act, g_act);
    cudaGetSymbolAddress((void**)&bnm, g_bnm);
    cudaGetSymbolAddress((void**)&bnv, g_bnv);
    cudaGetSymbolAddress((void**)&vlad, g_vlad);
    cudaGetSymbolAddress((void**)&cn, g_cn);
    cudaGetSymbolAddress((void**)&tn, g_tn);
    cudaGetSymbolAddress((void**)&part, g_part);

    static PoolParams pp;
    {
        static int perm1[N1];
        static int perm2[N2];
        np_permutation(1u, N1, perm1);
        np_permutation(2u, N2, perm2);
        for (int i = 0; i < 1024; i++) pp.p1[i] = perm1[i];
        for (int i = 0; i < 256;  i++) pp.p2[i] = perm2[i];
    }

    const float* nd1 = ndirs + 32 * 3;
    const float* nd2 = ndirs + 96 * 3;
    const float* nd3 = ndirs + 224 * 3;
    const float* nd4 = ndirs + 480 * 3;

    // ================= stage 1 (4096 pts) =================
    // knn1 + pools/ndirs init + conv_surface fused
    knn_init_surf_kernel<<<dim3(N1 / 128, BATCH), 128>>>(pp, dir0, dir1, dir2, dir3, dir4, x, nb, fa);
    gemm128_kernel<<<dim3(1, BATCH * N1 / 128), 256>>>(fa, W1, b1, fo, BATCH * N1, 32, 128);
    conv_act_kernel<<<BATCH * N1 / 16, 256>>>(x, nb, nd1, fo, fb, N1, 64, 16, 1);
    gather_max_pool_kernel<<<(BATCH * N2 * 16 + 255) / 256, 256>>>(fb, nb, pool1, x, fa, v2, N1, N2, 64);

    // ================= stage 2 (1024 pts) =================
    knn_kernel<<<dim3(N2 / 128, BATCH), 128>>>(v2, N2, nb);
    gemm128_kernel<<<dim3(2, BATCH * N2 / 128), 256>>>(fa, W2, b2, fo, BATCH * N2, 64, 256);
    conv_act_kernel<<<BATCH * N2 / 8, 256>>>(v2, nb, nd2, fo, fb, N2, 128, 8, 1);
    gemm128_kernel<<<dim3(4, BATCH * N2 / 128), 256>>>(fb, W3, b3, fo, BATCH * N2, 128, 512);
    conv_act_kernel<<<BATCH * N2 / 4, 256>>>(v2, nb, nd3, fo, fa, N2, 256, 4, 1);
    gather_max_pool_kernel<<<(BATCH * N3 * 64 + 255) / 256, 256>>>(fa, nb, pool2, v2, fb, v3, N2, N3, 256);

    // ================= stage 3 (256 pts) =================
    knn_kernel<<<dim3(N3 / 128, BATCH), 128>>>(v3, N3, nb);
    gemm128_kernel<<<dim3(16, BATCH * N3 / 128), 256>>>(fb, W4, b4, fo, BATCH * N3, 256, 2048);
    conv_act_kernel<<<BATCH * N3, 256>>>(v3, nb, nd4, fo, fa, N3, 1024, 1, 0);

    // ---- GeM -> y ----
    gem_kernel<<<BATCH, 256>>>(fa, gem_p, out);

    // ================= NetVLAD =================
    gemm_kahan_kernel<<<dim3(1, BATCH * N3 / 32), 256>>>(fa, cluster_w, act, BATCH * N3, 1024, 64);
    bn1_stats_kernel<<<64, 256>>>(act, bnm, bnv, BATCH * N3);
    bn_softmax_kernel<<<BATCH * N3 / 4, 256>>>(act, bnm, bnv, bn1_g, bn1_b);
    vlad_kernel<<<dim3(256, BATCH), 256>>>(act, fa, cluster_w2, vlad);
    colnorm_tn_kernel<<<BATCH, 1024>>>(vlad, cn, tn);
    skinny8_norm_kernel<<<dim3(4, 64), 256>>>(vlad, hidden_w, cn, tn, part, 65536, 1024);
    skinny8_gate_kernel<<<4, 256>>>(part, bn2_g, bn2_b, gating_w, gbn_g, gbn_b, out + BATCH * 1024);
}

// round 15
// speedup vs baseline: 1.0333x; 1.0333x over previous
#include <cuda_runtime.h>
#include <math.h>
#include <stdint.h>

#define BATCH 8
#define KNNK 20
#define N1 4096
#define N2 1024
#define N3 256

// ======================= device scratch =======================
__device__ float g_fo[BATCH * 4096 * 128];
__device__ float g_fa[BATCH * 4096 * 64];
__device__ float g_fb[BATCH * 4096 * 64];
__device__ int   g_nb[BATCH * 4096 * KNNK];
__device__ float g_ndirs[1504 * 3];
__device__ int   g_pool1[1024];
__device__ int   g_pool2[256];
__device__ float g_act[BATCH * 256 * 64];
__device__ float g_bnm[64];
__device__ float g_bnv[64];
__device__ float g_vlad[BATCH * 1024 * 64];
__device__ float g_cn[BATCH * 64];
__device__ float g_tn[BATCH];
__device__ float g_part[64 * BATCH * 1024];
__device__ float g_v2[BATCH * 1024 * 3];
__device__ float g_v3[BATCH * 256 * 3];

__device__ __forceinline__ void kadd(float& s, float& c, float v) {
    float y = __fadd_rn(v, -c);
    float t = __fadd_rn(s, y);
    c = __fadd_rn(__fadd_rn(t, -s), -y);
    s = t;
}

struct PoolParams { int p1[1024]; int p2[256]; };

// ======================= KNN body (R5/R7 exact form) =======================
#define KNN_TILE 128
__device__ __forceinline__ void knn_core(const float* __restrict__ v, int N,
                                         float4* sp, int* bi_out) {
    int b = blockIdx.y;
    int i = blockIdx.x * blockDim.x + threadIdx.x;
    const float* vb = v + (size_t)b * N * 3;
    float xi = vb[i * 3], yi = vb[i * 3 + 1], zi = vb[i * 3 + 2];
    float sqi = __fadd_rn(__fadd_rn(__fmul_rn(xi, xi), __fmul_rn(yi, yi)), __fmul_rn(zi, zi));

    float bd[KNNK]; int bi_[KNNK];
#pragma unroll
    for (int t = 0; t < KNNK; t++) { bd[t] = INFINITY; bi_[t] = 0x7fffffff; }
    float worst_d = INFINITY; int wslot = 0;

    for (int base = 0; base < N; base += KNN_TILE) {
        {
            int t = threadIdx.x;
            float X = vb[(base + t) * 3], Y = vb[(base + t) * 3 + 1], Z = vb[(base + t) * 3 + 2];
            float S = __fadd_rn(__fadd_rn(__fmul_rn(X, X), __fmul_rn(Y, Y)), __fmul_rn(Z, Z));
            sp[t] = make_float4(X, Y, Z, S);
        }
        __syncthreads();
        for (int t = 0; t < KNN_TILE; t += 4) {
            float d4_[4];
#pragma unroll
            for (int u = 0; u < 4; u++) {
                float4 q = sp[t + u];
                float dot = fmaf(zi, q.z, fmaf(yi, q.y, __fmul_rn(xi, q.x)));
                d4_[u] = __fadd_rn(__fadd_rn(sqi, q.w), -__fmul_rn(2.f, dot));
            }
#pragma unroll
            for (int u = 0; u < 4; u++) {
                int j = base + t + u;
                float d = d4_[u];
                if (j != i && d < worst_d) {
#pragma unroll
                    for (int s = 0; s < KNNK; s++) if (s == wslot) { bd[s] = d; bi_[s] = j; }
                    worst_d = bd[0]; wslot = 0;
#pragma unroll
                    for (int s = 1; s < KNNK; s++) {
                        if (bd[s] > worst_d) { worst_d = bd[s]; wslot = s; }
                    }
                }
            }
        }
        __syncthreads();
    }
#pragma unroll
    for (int t = 0; t < KNNK; t++) bi_out[t] = bi_[t];
}

__global__ void knn_kernel(const float* __restrict__ v, int N, int* __restrict__ nb) {
    __shared__ float4 sp[KNN_TILE];
    int bi_[KNNK];
    knn_core(v, N, sp, bi_);
    int b = blockIdx.y;
    int i = blockIdx.x * blockDim.x + threadIdx.x;
#pragma unroll
    for (int t = 0; t < KNNK; t++) nb[((size_t)b * N + i) * KNNK + t] = bi_[t];
}

// knn stage-1 + pools/ndirs init (block 0) + fused conv_surface
__global__ void knn_init_surf_kernel(PoolParams pp,
                                     const float* __restrict__ d0, const float* __restrict__ d1,
                                     const float* __restrict__ d2, const float* __restrict__ d3,
                                     const float* __restrict__ d4,
                                     const float* __restrict__ v, int* __restrict__ nb,
                                     float* __restrict__ fm) {
    __shared__ float4 sp[KNN_TILE];
    __shared__ float sd0[32 * 3];
    if (blockIdx.x == 0 && blockIdx.y == 0) {
        for (int t = threadIdx.x; t < 1024; t += 128) g_pool1[t] = pp.p1[t];
        for (int t = threadIdx.x; t < 256;  t += 128) g_pool2[t] = pp.p2[t];
        for (int t = threadIdx.x; t < 1504; t += 128) {
            const float* src; int F, off, f;
            if      (t < 32)  { src = d0; F = 32;   off = 0;   f = t; }
            else if (t < 96)  { src = d1; F = 64;   off = 32;  f = t - 32; }
            else if (t < 224) { src = d2; F = 128;  off = 96;  f = t - 96; }
            else if (t < 480) { src = d3; F = 256;  off = 224; f = t - 224; }
            else              { src = d4; F = 1024; off = 480; f = t - 480; }
            float a = src[f], b = src[F + f], c = src[2 * F + f];
            float n = fmaxf(sqrtf(a * a + b * b + c * c), 1e-12f);
            g_ndirs[(off + f) * 3]     = a / n;
            g_ndirs[(off + f) * 3 + 1] = b / n;
            g_ndirs[(off + f) * 3 + 2] = c / n;
        }
    }
    if (threadIdx.x < 32) {
        int f = threadIdx.x;
        float a = d0[f], b = d0[32 + f], c = d0[64 + f];
        float n = fmaxf(sqrtf(a * a + b * b + c * c), 1e-12f);
        sd0[f * 3] = a / n; sd0[f * 3 + 1] = b / n; sd0[f * 3 + 2] = c / n;
    }
    int bi_[KNNK];
    knn_core(v, N1, sp, bi_);
    int b = blockIdx.y;
    int i = blockIdx.x * blockDim.x + threadIdx.x;
#pragma unroll
    for (int t = 0; t < KNNK; t++) nb[((size_t)b * N1 + i) * KNNK + t] = bi_[t];

    const float* vb = v + (size_t)b * N1 * 3;
    float sdx[KNNK], sdy[KNNK], sdz[KNNK];
#pragma unroll
    for (int k = 0; k < KNNK; k++) {
        int j = bi_[k];
        float dx = vb[j * 3] - vb[i * 3];
        float dy = vb[j * 3 + 1] - vb[i * 3 + 1];
        float dz = vb[j * 3 + 2] - vb[i * 3 + 2];
        float nm = fmaxf(sqrtf(dx * dx + dy * dy + dz * dz), 1e-12f);
        sdx[k] = dx / nm; sdy[k] = dy / nm; sdz[k] = dz / nm;
    }
    float* fmrow = fm + ((size_t)b * N1 + i) * 32;
    for (int f = 0; f < 32; f++) {
        float d0v = sd0[f * 3], d1v = sd0[f * 3 + 1], d2v = sd0[f * 3 + 2];
        float m = 0.f;
#pragma unroll
        for (int k = 0; k < KNNK; k++) {
            float th = fmaxf(sdx[k] * d0v + sdy[k] * d1v + sdz[k] * d2v, 0.f);
            m = fmaxf(m, th);
        }
        fmrow[f] = m;
    }
}

// ======================= conv_layer activation: float4 channels per thread ==============
__global__ void conv_act_kernel(const float* __restrict__ v, const int* __restrict__ nb,
                                const float* __restrict__ ndirs, const float* __restrict__ fo,
                                float* __restrict__ out, int N, int OC, int G, int relu_out) {
    int C = 2 * OC;
    __shared__ float sdx[320], sdy[320], sdz[320];
    __shared__ int sj[320];
    int p0 = blockIdx.x * G;
    int t = threadIdx.x;
    for (int e = t; e < G * KNNK; e += 256) {
        int g = e / KNNK, k = e % KNNK;
        int p = p0 + g; int b = p / N; int n = p % N;
        const float* vb = v + (size_t)b * N * 3;
        int j = nb[(size_t)p * KNNK + k];
        sj[e] = b * N + j;
        float dx = vb[j * 3] - vb[n * 3];
        float dy = vb[j * 3 + 1] - vb[n * 3 + 1];
        float dz = vb[j * 3 + 2] - vb[n * 3 + 2];
        float nm = fmaxf(sqrtf(dx * dx + dy * dy + dz * dz), 1e-12f);
        sdx[e] = dx / nm; sdy[e] = dy / nm; sdz[e] = dz / nm;
    }
    __syncthreads();
    int TP = 256 / G;
    int g = t / TP, fq = t % TP;
    int p = p0 + g;
    int kb = g * KNNK;
    int OCq = OC / 4;
    const float* forow = fo + (size_t)p * C;
    for (int f4 = fq; f4 < OCq; f4 += TP) {
        int f = f4 * 4;
        float4 dA = *(const float4*)&ndirs[f * 3];
        float4 dB = *(const float4*)&ndirs[f * 3 + 4];
        float4 dC = *(const float4*)&ndirs[f * 3 + 8];
        float m0 = -INFINITY, m1 = -INFINITY, m2 = -INFINITY, m3 = -INFINITY;
#pragma unroll
        for (int k = 0; k < KNNK; k++) {
            float sx = sdx[kb + k], sy = sdy[kb + k], sz = sdz[kb + k];
            float4 fs = *(const float4*)&fo[(size_t)sj[kb + k] * C + OC + f];
            float th0 = fmaxf(sx * dA.x + sy * dA.y + sz * dA.z, 0.f);
            float th1 = fmaxf(sx * dA.w + sy * dB.x + sz * dB.y, 0.f);
            float th2 = fmaxf(sx * dB.z + sy * dB.w + sz * dC.x, 0.f);
            float th3 = fmaxf(sx * dC.y + sy * dC.z + sz * dC.w, 0.f);
            m0 = fmaxf(m0, th0 * fs.x);
            m1 = fmaxf(m1, th1 * fs.y);
            m2 = fmaxf(m2, th2 * fs.z);
            m3 = fmaxf(m3, th3 * fs.w);
        }
        float4 fr = *(const float4*)&forow[f];
        float4 val = make_float4(fr.x + m0, fr.y + m1, fr.z + m2, fr.w + m3);
        if (relu_out) {
            val.x = fmaxf(val.x, 0.f); val.y = fmaxf(val.y, 0.f);
            val.z = fmaxf(val.z, 0.f); val.w = fmaxf(val.w, 0.f);
        }
        *(float4*)&out[(size_t)p * OC + f] = val;
    }
}

// ======================= fused gather_max + pool + coord gather =======================
__global__ void gather_max_pool_kernel(const float* __restrict__ fm, const int* __restrict__ nb,
                                       const int* __restrict__ pool, const float* __restrict__ vin,
                                       float* __restrict__ out, float* __restrict__ vout,
                                       int Nin, int Nout, int F) {
    int F4 = F / 4;
    int idx = blockIdx.x * blockDim.x + threadIdx.x;
    int tot = BATCH * Nout * F4;
    if (idx < tot) {
        int f4 = idx % F4; int r = idx / F4; int b = r / Nout; int pp = r % Nout;
        int row = pool[pp];
        const int* nbp = nb + ((size_t)b * Nin + row) * KNNK;
        float4 m = make_float4(-INFINITY, -INFINITY, -INFINITY, -INFINITY);
#pragma unroll
        for (int k = 0; k < KNNK; k++) {
            const float4 vv = *(const float4*)&fm[((size_t)b * Nin + nbp[k]) * F + f4 * 4];
            m.x = fmaxf(m.x, vv.x); m.y = fmaxf(m.y, vv.y);
            m.z = fmaxf(m.z, vv.z); m.w = fmaxf(m.w, vv.w);
        }
        *(float4*)&out[(size_t)r * F + f4 * 4] = m;
    }
    if (idx < BATCH * Nout * 3) {
        int f = idx % 3; int r = idx / 3; int b = r / Nout; int pp = r % Nout;
        vout[idx] = vin[((size_t)b * Nin + pool[pp]) * 3 + f];
    }
}

// ======================= 128x128 SGEMM (R12 winner form) =======================
#define GT 132
__global__ __launch_bounds__(256, 2) void gemm128_kernel(
        const float* __restrict__ A, const float* __restrict__ B,
        const float* __restrict__ bias, float* __restrict__ C,
        int M, int K, int N) {
    __shared__ float As[8][GT];
    __shared__ float Bs[8][GT];
    int row0 = blockIdx.y * 128, col0 = blockIdx.x * 128;
    int tid = threadIdx.x;
    int tx = tid % 16, ty = tid / 16;
    int arow = tid >> 1, acol = (tid & 1) * 4;
    int brow = tid >> 5, bcol = (tid & 31) * 4;
    float4 pa = *(const float4*)&A[(size_t)(row0 + arow) * K + acol];
    float4 pb = *(const float4*)&B[(size_t)brow * N + col0 + bcol];
    float acc[8][8] = {};
    for (int k0 = 0; k0 < K; k0 += 8) {
        As[acol][arow] = pa.x; As[acol + 1][arow] = pa.y;
        As[acol + 2][arow] = pa.z; As[acol + 3][arow] = pa.w;
        *(float4*)&Bs[brow][bcol] = pb;
        __syncthreads();
        if (k0 + 8 < K) {
            pa = *(const float4*)&A[(size_t)(row0 + arow) * K + k0 + 8 + acol];
            pb = *(const float4*)&B[(size_t)(k0 + 8 + brow) * N + col0 + bcol];
        }
#pragma unroll
        for (int kk = 0; kk < 8; kk++) {
            float a[8], bb[8];
            *(float4*)&a[0] = *(const float4*)&As[kk][ty * 8];
            *(float4*)&a[4] = *(const float4*)&As[kk][ty * 8 + 4];
            *(float4*)&bb[0] = *(const float4*)&Bs[kk][tx * 8];
            *(float4*)&bb[4] = *(const float4*)&Bs[kk][tx * 8 + 4];
#pragma unroll
            for (int i = 0; i < 8; i++)
#pragma unroll
                for (int j = 0; j < 8; j++) acc[i][j] = fmaf(a[i], bb[j], acc[i][j]);
        }
        __syncthreads();
    }
    float bz[8];
    if (bias) {
        *(float4*)&bz[0] = *(const float4*)&bias[col0 + tx * 8];
        *(float4*)&bz[4] = *(const float4*)&bias[col0 + tx * 8 + 4];
    } else {
#pragma unroll
        for (int j = 0; j < 8; j++) bz[j] = 0.f;
    }
#pragma unroll
    for (int i = 0; i < 8; i++) {
        float* crow = &C[(size_t)(row0 + ty * 8 + i) * N + col0 + tx * 8];
        float4 r0 = make_float4(acc[i][0] + bz[0], acc[i][1] + bz[1], acc[i][2] + bz[2], acc[i][3] + bz[3]);
        float4 r1 = make_float4(acc[i][4] + bz[4], acc[i][5] + bz[5], acc[i][6] + bz[6], acc[i][7] + bz[7]);
        *(float4*)crow = r0;
        *(float4*)(crow + 4) = r1;
    }
}

// ======================= cluster GEMM: 32x64 tiles, tile-compensated =======================
__global__ void gemm_kahan_kernel(const float* __restrict__ A, const float* __restrict__ B,
                                  float* __restrict__ C, int M, int K, int N) {
    __shared__ float As[16][36];
    __shared__ float Bs[16][68];
    int row0 = blockIdx.y * 32;
    int tid = threadIdx.x;
    int tx = tid % 16, ty = tid / 16;
    float acc[2][4] = {}; float cmp[2][4] = {};
    int ar = tid >> 2, ac4 = (tid & 3) * 4;
    int br = tid >> 4, bc4 = (tid & 15) * 4;
    for (int k0 = 0; k0 < K; k0 += 16) {
        if (tid < 128) {
            float4 av = *(const float4*)&A[(size_t)(row0 + ar) * K + k0 + ac4];
            As[ac4][ar] = av.x; As[ac4 + 1][ar] = av.y; As[ac4 + 2][ar] = av.z; As[ac4 + 3][ar] = av.w;
        }
        *(float4*)&Bs[br][bc4] = *(const float4*)&B[(size_t)(k0 + br) * N + bc4];
        __syncthreads();
        float tacc[2][4] = {};
#pragma unroll
        for (int kk = 0; kk < 16; kk++) {
            float a[2], bb[4];
            a[0] = As[kk][ty * 2]; a[1] = As[kk][ty * 2 + 1];
            float4 b4 = *(const float4*)&Bs[kk][tx * 4];
            bb[0] = b4.x; bb[1] = b4.y; bb[2] = b4.z; bb[3] = b4.w;
#pragma unroll
            for (int i = 0; i < 2; i++)
#pragma unroll
                for (int j = 0; j < 4; j++) tacc[i][j] = fmaf(a[i], bb[j], tacc[i][j]);
        }
#pragma unroll
        for (int i = 0; i < 2; i++)
#pragma unroll
            for (int j = 0; j < 4; j++) kadd(acc[i][j], cmp[i][j], tacc[i][j]);
        __syncthreads();
    }
#pragma unroll
    for (int i = 0; i < 2; i++)
#pragma unroll
        for (int j = 0; j < 4; j++)
            C[(size_t)(row0 + ty * 2 + i) * N + tx * 4 + j] = acc[i][j];
}

// ======================= GeM =======================
__device__ __forceinline__ float fast_pow(float x, float p) {
    return exp2f(p * log2f(x));
}
__global__ void gem_kernel(const float* __restrict__ fm4, const float* __restrict__ gem_p,
                           float* __restrict__ y) {
    int b = blockIdx.x;
    int c4 = threadIdx.x * 4;
    float p = gem_p[0];
    bool p3 = (p == 3.0f);
    float s[4] = {}; float sc[4] = {};
    for (int nc = 0; nc < 8; nc++) {
        float t[4] = {};
        for (int n = nc * 32; n < nc * 32 + 32; n++) {
            float4 f = *(const float4*)&fm4[((size_t)b * N3 + n) * 1024 + c4];
            float fx = fmaxf(f.x, 1e-6f), fy = fmaxf(f.y, 1e-6f);
            float fz = fmaxf(f.z, 1e-6f), fw = fmaxf(f.w, 1e-6f);
            if (p3) {
                t[0] = __fadd_rn(t[0], fx * fx * fx);
                t[1] = __fadd_rn(t[1], fy * fy * fy);
                t[2] = __fadd_rn(t[2], fz * fz * fz);
                t[3] = __fadd_rn(t[3], fw * fw * fw);
            } else {
                t[0] = __fadd_rn(t[0], fast_pow(fx, p));
                t[1] = __fadd_rn(t[1], fast_pow(fy, p));
                t[2] = __fadd_rn(t[2], fast_pow(fz, p));
                t[3] = __fadd_rn(t[3], fast_pow(fw, p));
            }
        }
#pragma unroll
        for (int u = 0; u < 4; u++) kadd(s[u], sc[u], t[u]);
    }
    float4 r;
    if (p3) {
        r.x = cbrtf(s[0] / (float)N3); r.y = cbrtf(s[1] / (float)N3);
        r.z = cbrtf(s[2] / (float)N3); r.w = cbrtf(s[3] / (float)N3);
    } else {
        float ip = 1.f / p;
        r.x = fast_pow(s[0] / (float)N3, ip); r.y = fast_pow(s[1] / (float)N3, ip);
        r.z = fast_pow(s[2] / (float)N3, ip); r.w = fast_pow(s[3] / (float)N3, ip);
    }
    *(float4*)&y[b * 1024 + c4] = r;
}

// ======================= NetVLAD =======================
__global__ void bn1_stats_kernel(const float* __restrict__ act, float* __restrict__ mean,
                                 float* __restrict__ var, int rows) {
    int k = blockIdx.x;
    __shared__ double sd[256];
    float a = 0.f, ac = 0.f;
    for (int r = threadIdx.x; r < rows; r += 256) kadd(a, ac, act[(size_t)r * 64 + k]);
    sd[threadIdx.x] = (double)a; __syncthreads();
    for (int s = 128; s > 0; s >>= 1) {
        if (threadIdx.x < s) sd[threadIdx.x] += sd[threadIdx.x + s];
        __syncthreads();
    }
    float m = (float)(sd[0] / rows);
    __syncthreads();
    float q = 0.f, qc = 0.f;
    for (int r = threadIdx.x; r < rows; r += 256) {
        float d = __fadd_rn(act[(size_t)r * 64 + k], -m);
        kadd(q, qc, __fmul_rn(d, d));
    }
    sd[threadIdx.x] = (double)q; __syncthreads();
    for (int s = 128; s > 0; s >>= 1) {
        if (threadIdx.x < s) sd[threadIdx.x] += sd[threadIdx.x + s];
        __syncthreads();
    }
    if (threadIdx.x == 0) { mean[k] = m; var[k] = (float)(sd[0] / rows); }
}

__global__ void bn_softmax_kernel(float* __restrict__ act, const float* __restrict__ mean,
                                  const float* __restrict__ var, const float* __restrict__ g,
                                  const float* __restrict__ bb) {
    int r = blockIdx.x * 4 + threadIdx.x / 64;
    int k = threadIdx.x % 64;
    int rb = (threadIdx.x / 64) * 64;
    __shared__ float sv[256];
    float v = (act[(size_t)r * 64 + k] - mean[k]) * rsqrtf(var[k] + 1e-5f) * g[k] + bb[k];
    sv[threadIdx.x] = v; __syncthreads();
    float mx = -INFINITY;
    for (int t = 0; t < 64; t++) mx = fmaxf(mx, sv[rb + t]);
    float e = expf(v - mx);
    __syncthreads(); sv[threadIdx.x] = e; __syncthreads();
    float s = 0.f, sc = 0.f;
    for (int t = 0; t < 64; t++) kadd(s, sc, sv[rb + t]);
    act[(size_t)r * 64 + k] = e / s;
}

// vlad with asum computed in-block
__global__ void vlad_kernel(const float* __restrict__ act, const float* __restrict__ xv,
                            const float* __restrict__ cw2, float* __restrict__ vlad) {
    int b = blockIdx.y;
    int k = threadIdx.x % 64;
    int fi = threadIdx.x / 64;
    int f = blockIdx.x * 4 + fi;
    __shared__ float sasum[64];
    float s = 0.f, sc = 0.f;
    for (int m0 = 0; m0 < N3; m0 += 32) {
        float bs = 0.f;
#pragma unroll 8
        for (int m = m0; m < m0 + 32; m++) {
            bs = fmaf(act[((size_t)b * N3 + m) * 64 + k], xv[((size_t)b * N3 + m) * 1024 + f], bs);
        }
        kadd(s, sc, bs);
    }
    if (fi == 0) {
        float sa = 0.f, sac = 0.f;
        for (int m0 = 0; m0 < N3; m0 += 32) {
            float bsa = 0.f;
#pragma unroll 8
            for (int m = m0; m < m0 + 32; m++) bsa = __fadd_rn(bsa, act[((size_t)b * N3 + m) * 64 + k]);
            kadd(sa, sac, bsa);
        }
        sasum[k] = sa;
    }
    __syncthreads();
    s = __fadd_rn(s, -__fmul_rn(sasum[k], cw2[(size_t)f * 64 + k]));
    vlad[((size_t)b * 1024 + f) * 64 + k] = s;
}

// colnorm + tn fused
__global__ void colnorm_tn_kernel(const float* __restrict__ vlad, float* __restrict__ cn,
                                  float* __restrict__ tn) {
    int b = blockIdx.x; int tid = threadIdx.x;
    int k = tid % 64, grp = tid / 64;
    float s = 0.f, sc = 0.f;
    for (int q0 = 0; q0 < 64; q0 += 16) {
        float bs = 0.f;
#pragma unroll
        for (int q = q0; q < q0 + 16; q++) {
            int f = grp + q * 16;
            float v = vlad[((size_t)b * 1024 + f) * 64 + k];
            bs = fmaf(v, v, bs);
        }
        kadd(s, sc, bs);
    }
    __shared__ double sm[1024];
    __shared__ float scn[64];
    sm[tid] = (double)s; __syncthreads();
    if (grp == 0) {
        double t = 0.0;
        for (int g2 = 0; g2 < 16; g2++) t += sm[g2 * 64 + k];
        float cv = (float)t;
        cn[b * 64 + k] = cv;
        scn[k] = cv;
    }
    __syncthreads();
    if (tid == 0) {
        double t = 0.0;
        for (int k2 = 0; k2 < 64; k2++) {
            float c = scn[k2];
            float d = fmaxf(sqrtf(c), 1e-12f);
            t += (double)(c / (d * d));
        }
        tn[b] = (float)t;
    }
}

// hidden skinny GEMM with fused vlad normalization on smem load
#define SKC 1024
__global__ void skinny8_norm_kernel(const float* __restrict__ A, const float* __restrict__ W,
                                    const float* __restrict__ cn, const float* __restrict__ tn,
                                    float* __restrict__ part, int K, int N) {
    int j = blockIdx.x * 256 + threadIdx.x;
    int k0 = blockIdx.y * SKC;
    __shared__ float xs[BATCH * SKC];
    __shared__ float s1[BATCH * 64];
    __shared__ float s2[BATCH];
    if (threadIdx.x < 8) s2[threadIdx.x] = 1.f / fmaxf(sqrtf(tn[threadIdx.x]), 1e-12f);
    for (int t = threadIdx.x; t < BATCH * 64; t += 256)
        s1[t] = 1.f / fmaxf(sqrtf(cn[t]), 1e-12f);
    __syncthreads();
    for (int t = threadIdx.x; t < BATCH * SKC; t += 256) {
        int bb = t / SKC; int ii = t % SKC;
        int gi = k0 + ii; int k = gi & 63;
        xs[t] = A[(size_t)bb * K + gi] * s1[bb * 64 + k] * s2[bb];
    }
    __syncthreads();
    if (j < N) {
        float acc[BATCH] = {}; float cmp[BATCH] = {};
#pragma unroll 1
        for (int i0 = 0; i0 < SKC; i0 += 16) {
            float ba[BATCH] = {};
#pragma unroll 8
            for (int i = i0; i < i0 + 16; i++) {
                float w = W[(size_t)(k0 + i) * N + j];
#pragma unroll
                for (int bb = 0; bb < BATCH; bb++) ba[bb] = fmaf(xs[bb * SKC + i], w, ba[bb]);
            }
#pragma unroll
            for (int bb = 0; bb < BATCH; bb++) kadd(acc[bb], cmp[bb], ba[bb]);
        }
#pragma unroll
        for (int bb = 0; bb < BATCH; bb++) {
            part[(size_t)blockIdx.y * BATCH * N + bb * N + j] = acc[bb];
        }
    }
}

// gating skinny GEMM with fused bn2-from-partials + gate BN + sigmoid + multiply
__global__ void skinny8_gate_kernel(const float* __restrict__ part,
                                    const float* __restrict__ bn2_g, const float* __restrict__ bn2_b,
                                    const float* __restrict__ W,
                                    const float* __restrict__ gg, const float* __restrict__ gb,
                                    float* __restrict__ desc) {
    int j = blockIdx.x * 256 + threadIdx.x;
    __shared__ float xs[BATCH * 1024];
    for (int i = 0; i < 4; i++) {
        int jj = threadIdx.x + i * 256;
        float h[BATCH];
#pragma unroll
        for (int b = 0; b < BATCH; b++) {
            float s = 0.f, sc = 0.f;
            for (int c = 0; c < 64; c++) kadd(s, sc, part[(size_t)c * BATCH * 1024 + b * 1024 + jj]);
            h[b] = s;
        }
        double m = 0.0;
#pragma unroll
        for (int b = 0; b < BATCH; b++) m += (double)h[b];
        m /= BATCH;
        double q = 0.0;
#pragma unroll
        for (int b = 0; b < BATCH; b++) { double d = (double)h[b] - m; q += d * d; }
        q /= BATCH;
        float mf = (float)m;
        float inv = rsqrtf((float)q + 1e-5f);
#pragma unroll
        for (int b = 0; b < BATCH; b++)
            xs[b * 1024 + jj] = (h[b] - mf) * inv * bn2_g[jj] + bn2_b[jj];
    }
    __syncthreads();
    float acc[BATCH] = {}; float cmp[BATCH] = {};
#pragma unroll 1
    for (int i0 = 0; i0 < 1024; i0 += 16) {
        float ba[BATCH] = {};
#pragma unroll 4
        for (int i = i0; i < i0 + 16; i++) {
            float w = W[(size_t)i * 1024 + j];
#pragma unroll
            for (int bb = 0; bb < BATCH; bb++) ba[bb] = fmaf(xs[bb * 1024 + i], w, ba[bb]);
        }
#pragma unroll
        for (int bb = 0; bb < BATCH; bb++) kadd(acc[bb], cmp[bb], ba[bb]);
    }
    double m = 0.0;
#pragma unroll
    for (int bb = 0; bb < BATCH; bb++) m += (double)acc[bb];
    m /= BATCH;
    double q = 0.0;
#pragma unroll
    for (int bb = 0; bb < BATCH; bb++) { double d = (double)acc[bb] - m; q += d * d; }
    q /= BATCH;
    float mf = (float)m;
    float inv = rsqrtf((float)q + 1e-5f);
#pragma unroll
    for (int bb = 0; bb < BATCH; bb++) {
        float z = (acc[bb] - mf) * inv * gg[j] + gb[j];
        float s = 1.f / (1.f + expf(-z));
        desc[bb * 1024 + j] = xs[bb * 1024 + j] * s;
    }
}

// ======================= host: numpy-compatible MT19937 pools =======================
struct MTState { uint32_t mt[624]; int idx; };

static void mt_seed(MTState& s, uint32_t seed) {
    for (int p = 0; p < 624; p++) {
        s.mt[p] = seed;
        seed = 1812433253u * (seed ^ (seed >> 30)) + (uint32_t)p + 1u;
    }
    s.idx = 624;
}
static uint32_t mt_next(MTState& s) {
    if (s.idx >= 624) {
        for (int i = 0; i < 624; i++) {
            uint32_t y = (s.mt[i] & 0x80000000u) | (s.mt[(i + 1) % 624] & 0x7fffffffu);
            uint32_t v = s.mt[(i + 397) % 624] ^ (y >> 1);
            if (y & 1u) v ^= 0x9908b0dfu;
            s.mt[i] = v;
        }
        s.idx = 0;
    }
    uint32_t y = s.mt[s.idx++];
    y ^= y >> 11;
    y ^= (y << 7) & 0x9d2c5680u;
    y ^= (y << 15) & 0xefc60000u;
    y ^= y >> 18;
    return y;
}
static uint32_t rk_interval(MTState& s, uint32_t mx) {
    if (mx == 0) return 0;
    uint32_t mask = mx;
    mask |= mask >> 1; mask |= mask >> 2; mask |= mask >> 4;
    mask |= mask >> 8; mask |= mask >> 16;
    uint32_t v;
    while ((v = (mt_next(s) & mask)) > mx) {}
    return v;
}
static void np_permutation(uint32_t seed, int n, int* out) {
    for (int i = 0; i < n; i++) out[i] = i;
    MTState s; mt_seed(s, seed);
    for (int i = n - 1; i >= 1; i--) {
        uint32_t j = rk_interval(s, (uint32_t)i);
        int t = out[i]; out[i] = out[(int)j]; out[(int)j] = t;
    }
}

// ======================= launch (with fork/join graph parallelism) =======================
extern "C" void kernel_launch(void* const* d_in, const int* in_sizes, int n_in,
                              void* d_out, int out_size) {
    const float* x         = (const float*)d_in[0];
    const float* dir0      = (const float*)d_in[1];
    const float* W1        = (const float*)d_in[2];
    const float* b1        = (const float*)d_in[3];
    const float* dir1      = (const float*)d_in[4];
    const float* W2        = (const float*)d_in[5];
    const float* b2        = (const float*)d_in[6];
    const float* dir2      = (const float*)d_in[7];
    const float* W3        = (const float*)d_in[8];
    const float* b3        = (const float*)d_in[9];
    const float* dir3      = (const float*)d_in[10];
    const float* W4        = (const float*)d_in[11];
    const float* b4        = (const float*)d_in[12];
    const float* dir4      = (const float*)d_in[13];
    const float* gem_p     = (const float*)d_in[14];
    const float* cluster_w = (const float*)d_in[15];
    const float* cluster_w2= (const float*)d_in[16];
    const float* hidden_w  = (const float*)d_in[17];
    const float* bn1_g     = (const float*)d_in[18];
    const float* bn1_b     = (const float*)d_in[19];
    const float* bn2_g     = (const float*)d_in[20];
    const float* bn2_b     = (const float*)d_in[21];
    const float* gating_w  = (const float*)d_in[22];
    const float* gbn_g     = (const float*)d_in[23];
    const float* gbn_b     = (const float*)d_in[24];
    float* out = (float*)d_out;

    float *fo, *fa, *fb, *ndirs, *v2, *v3, *act, *bnm, *bnv, *vlad, *cn, *tn, *part;
    int *nb, *pool1, *pool2;
    cudaGetSymbolAddress((void**)&fo, g_fo);
    cudaGetSymbolAddress((void**)&fa, g_fa);
    cudaGetSymbolAddress((void**)&fb, g_fb);
    cudaGetSymbolAddress((void**)&nb, g_nb);
    cudaGetSymbolAddress((void**)&ndirs, g_ndirs);
    cudaGetSymbolAddress((void**)&pool1, g_pool1);
    cudaGetSymbolAddress((void**)&pool2, g_pool2);
    cudaGetSymbolAddress((void**)&v2, g_v2);
    cudaGetSymbolAddress((void**)&v3, g_v3);
    cudaGetSymbolAddress((void**)&act, g_act);
    cudaGetSymbolAddress((void**)&bnm, g_bnm);
    cudaGetSymbolAddress((void**)&bnv, g_bnv);
    cudaGetSymbolAddress((void**)&vlad, g_vlad);
    cudaGetSymbolAddress((void**)&cn, g_cn);
    cudaGetSymbolAddress((void**)&tn, g_tn);
    cudaGetSymbolAddress((void**)&part, g_part);

    static PoolParams pp;
    {
        static int perm1[N1];
        static int perm2[N2];
        np_permutation(1u, N1, perm1);
        np_permutation(2u, N2, perm2);
        for (int i = 0; i < 1024; i++) pp.p1[i] = perm1[i];
        for (int i = 0; i < 256;  i++) pp.p2[i] = perm2[i];
    }

    // side stream + events, created once on the first (uncaptured) correctness call
    static cudaStream_t sside = nullptr;
    static cudaEvent_t ev[6];
    if (sside == nullptr) {
        cudaStreamCreateWithFlags(&sside, cudaStreamNonBlocking);
        for (int i = 0; i < 6; i++) cudaEventCreateWithFlags(&ev[i], cudaEventDisableTiming);
    }

    const float* nd1 = ndirs + 32 * 3;
    const float* nd2 = ndirs + 96 * 3;
    const float* nd3 = ndirs + 224 * 3;
    const float* nd4 = ndirs + 480 * 3;

    // ================= stage 1 (4096 pts) =================
    knn_init_surf_kernel<<<dim3(N1 / 128, BATCH), 128>>>(pp, dir0, dir1, dir2, dir3, dir4, x, nb, fa);
    gemm128_kernel<<<dim3(1, BATCH * N1 / 128), 256>>>(fa, W1, b1, fo, BATCH * N1, 32, 128);
    conv_act_kernel<<<BATCH * N1 / 16, 256>>>(x, nb, nd1, fo, fb, N1, 64, 16, 1);
    gather_max_pool_kernel<<<(BATCH * N2 * 16 + 255) / 256, 256>>>(fb, nb, pool1, x, fa, v2, N1, N2, 64);

    // ================= stage 2 (1024 pts) =================
    // fork: knn2 (reads v2) runs concurrently with gemm W2 (reads fa)
    cudaEventRecord(ev[0], 0);
    cudaStreamWaitEvent(sside, ev[0], 0);
    knn_kernel<<<dim3(N2 / 128, BATCH), 128, 0, sside>>>(v2, N2, nb);
    cudaEventRecord(ev[1], sside);
    gemm128_kernel<<<dim3(2, BATCH * N2 / 128), 256>>>(fa, W2, b2, fo, BATCH * N2, 64, 256);
    cudaStreamWaitEvent(0, ev[1], 0);   // conv_act needs both nb and fo
    conv_act_kernel<<<BATCH * N2 / 8, 256>>>(v2, nb, nd2, fo, fb, N2, 128, 8, 1);
    gemm128_kernel<<<dim3(4, BATCH * N2 / 128), 256>>>(fb, W3, b3, fo, BATCH * N2, 128, 512);
    conv_act_kernel<<<BATCH * N2 / 4, 256>>>(v2, nb, nd3, fo, fa, N2, 256, 4, 1);
    gather_max_pool_kernel<<<(BATCH * N3 * 64 + 255) / 256, 256>>>(fa, nb, pool2, v2, fb, v3, N2, N3, 256);

    // ================= stage 3 (256 pts) =================
    // fork: knn3 (reads v3) runs concurrently with gemm W4 (reads fb)
    cudaEventRecord(ev[2], 0);
    cudaStreamWaitEvent(sside, ev[2], 0);
    knn_kernel<<<dim3(N3 / 128, BATCH), 128, 0, sside>>>(v3, N3, nb);
    cudaEventRecord(ev[3], sside);
    gemm128_kernel<<<dim3(16, BATCH * N3 / 128), 256>>>(fb, W4, b4, fo, BATCH * N3, 256, 2048);
    cudaStreamWaitEvent(0, ev[3], 0);
    conv_act_kernel<<<BATCH * N3, 256>>>(v3, nb, nd4, fo, fa, N3, 1024, 1, 0);

    // fork: GeM (y output, reads fa) runs concurrently with the entire NetVLAD tail
    cudaEventRecord(ev[4], 0);
    cudaStreamWaitEvent(sside, ev[4], 0);
    gem_kernel<<<BATCH, 256, 0, sside>>>(fa, gem_p, out);
    cudaEventRecord(ev[5], sside);

    // ================= NetVLAD =================
    gemm_kahan_kernel<<<dim3(1, BATCH * N3 / 32), 256>>>(fa, cluster_w, act, BATCH * N3, 1024, 64);
    bn1_stats_kernel<<<64, 256>>>(act, bnm, bnv, BATCH * N3);
    bn_softmax_kernel<<<BATCH * N3 / 4, 256>>>(act, bnm, bnv, bn1_g, bn1_b);
    vlad_kernel<<<dim3(256, BATCH), 256>>>(act, fa, cluster_w2, vlad);
    colnorm_tn_kernel<<<BATCH, 1024>>>(vlad, cn, tn);
    skinny8_norm_kernel<<<dim3(4, 64), 256>>>(vlad, hidden_w, cn, tn, part, 65536, 1024);
    skinny8_gate_kernel<<<4, 256>>>(part, bn2_g, bn2_b, gating_w, gbn_g, gbn_b, out + BATCH * 1024);

    // join the GeM branch so capture ends with a single frontier
    cudaStreamWaitEvent(0, ev[5], 0);
}

// round 16
// speedup vs baseline: 1.0346x; 1.0012x over previous
#include <cuda_runtime.h>
#include <math.h>
#include <stdint.h>

#define BATCH 8
#define KNNK 20
#define N1 4096
#define N2 1024
#define N3 256

// ======================= device scratch =======================
__device__ float g_fo[BATCH * 4096 * 128];
__device__ float g_fa[BATCH * 4096 * 64];
__device__ float g_fb[BATCH * 4096 * 64];
__device__ int   g_nb1[BATCH * 4096 * KNNK];
__device__ int   g_nb2[BATCH * 1024 * KNNK];
__device__ int   g_nb3[BATCH * 256 * KNNK];
__device__ float g_ndirs[1504 * 3];
__device__ int   g_pool1[1024];
__device__ int   g_pool2[256];
__device__ float g_act[BATCH * 256 * 64];
__device__ float g_bnm[64];
__device__ float g_bnv[64];
__device__ float g_vlad[BATCH * 1024 * 64];
__device__ float g_cn[BATCH * 64];
__device__ float g_tn[BATCH];
__device__ float g_part[64 * BATCH * 1024];
__device__ float g_v2[BATCH * 1024 * 3];
__device__ float g_v3[BATCH * 256 * 3];

__device__ __forceinline__ void kadd(float& s, float& c, float v) {
    float y = __fadd_rn(v, -c);
    float t = __fadd_rn(s, y);
    c = __fadd_rn(__fadd_rn(t, -s), -y);
    s = t;
}

struct PoolParams { int p1[1024]; int p2[256]; };

// ======================= KNN body (R5/R7 exact form) =======================
#define KNN_TILE 128
__device__ __forceinline__ void knn_core(const float* __restrict__ v, int N,
                                         float4* sp, int* bi_out) {
    int b = blockIdx.y;
    int i = blockIdx.x * blockDim.x + threadIdx.x;
    const float* vb = v + (size_t)b * N * 3;
    float xi = vb[i * 3], yi = vb[i * 3 + 1], zi = vb[i * 3 + 2];
    float sqi = __fadd_rn(__fadd_rn(__fmul_rn(xi, xi), __fmul_rn(yi, yi)), __fmul_rn(zi, zi));

    float bd[KNNK]; int bi_[KNNK];
#pragma unroll
    for (int t = 0; t < KNNK; t++) { bd[t] = INFINITY; bi_[t] = 0x7fffffff; }
    float worst_d = INFINITY; int wslot = 0;

    for (int base = 0; base < N; base += KNN_TILE) {
        {
            int t = threadIdx.x;
            float X = vb[(base + t) * 3], Y = vb[(base + t) * 3 + 1], Z = vb[(base + t) * 3 + 2];
            float S = __fadd_rn(__fadd_rn(__fmul_rn(X, X), __fmul_rn(Y, Y)), __fmul_rn(Z, Z));
            sp[t] = make_float4(X, Y, Z, S);
        }
        __syncthreads();
        for (int t = 0; t < KNN_TILE; t += 4) {
            float d4_[4];
#pragma unroll
            for (int u = 0; u < 4; u++) {
                float4 q = sp[t + u];
                float dot = fmaf(zi, q.z, fmaf(yi, q.y, __fmul_rn(xi, q.x)));
                d4_[u] = __fadd_rn(__fadd_rn(sqi, q.w), -__fmul_rn(2.f, dot));
            }
#pragma unroll
            for (int u = 0; u < 4; u++) {
                int j = base + t + u;
                float d = d4_[u];
                if (j != i && d < worst_d) {
#pragma unroll
                    for (int s = 0; s < KNNK; s++) if (s == wslot) { bd[s] = d; bi_[s] = j; }
                    worst_d = bd[0]; wslot = 0;
#pragma unroll
                    for (int s = 1; s < KNNK; s++) {
                        if (bd[s] > worst_d) { worst_d = bd[s]; wslot = s; }
                    }
                }
            }
        }
        __syncthreads();
    }
#pragma unroll
    for (int t = 0; t < KNNK; t++) bi_out[t] = bi_[t];
}

__global__ void knn_kernel(const float* __restrict__ v, int N, int* __restrict__ nb) {
    __shared__ float4 sp[KNN_TILE];
    int bi_[KNNK];
    knn_core(v, N, sp, bi_);
    int b = blockIdx.y;
    int i = blockIdx.x * blockDim.x + threadIdx.x;
#pragma unroll
    for (int t = 0; t < KNNK; t++) nb[((size_t)b * N + i) * KNNK + t] = bi_[t];
}

// knn stage-1 + pools/ndirs init (block 0) + fused conv_surface
__global__ void knn_init_surf_kernel(PoolParams pp,
                                     const float* __restrict__ d0, const float* __restrict__ d1,
                                     const float* __restrict__ d2, const float* __restrict__ d3,
                                     const float* __restrict__ d4,
                                     const float* __restrict__ v, int* __restrict__ nb,
                                     float* __restrict__ fm) {
    __shared__ float4 sp[KNN_TILE];
    __shared__ float sd0[32 * 3];
    if (blockIdx.x == 0 && blockIdx.y == 0) {
        for (int t = threadIdx.x; t < 1024; t += 128) g_pool1[t] = pp.p1[t];
        for (int t = threadIdx.x; t < 256;  t += 128) g_pool2[t] = pp.p2[t];
        for (int t = threadIdx.x; t < 1504; t += 128) {
            const float* src; int F, off, f;
            if      (t < 32)  { src = d0; F = 32;   off = 0;   f = t; }
            else if (t < 96)  { src = d1; F = 64;   off = 32;  f = t - 32; }
            else if (t < 224) { src = d2; F = 128;  off = 96;  f = t - 96; }
            else if (t < 480) { src = d3; F = 256;  off = 224; f = t - 224; }
            else              { src = d4; F = 1024; off = 480; f = t - 480; }
            float a = src[f], b = src[F + f], c = src[2 * F + f];
            float n = fmaxf(sqrtf(a * a + b * b + c * c), 1e-12f);
            g_ndirs[(off + f) * 3]     = a / n;
            g_ndirs[(off + f) * 3 + 1] = b / n;
            g_ndirs[(off + f) * 3 + 2] = c / n;
        }
    }
    if (threadIdx.x < 32) {
        int f = threadIdx.x;
        float a = d0[f], b = d0[32 + f], c = d0[64 + f];
        float n = fmaxf(sqrtf(a * a + b * b + c * c), 1e-12f);
        sd0[f * 3] = a / n; sd0[f * 3 + 1] = b / n; sd0[f * 3 + 2] = c / n;
    }
    int bi_[KNNK];
    knn_core(v, N1, sp, bi_);
    int b = blockIdx.y;
    int i = blockIdx.x * blockDim.x + threadIdx.x;
#pragma unroll
    for (int t = 0; t < KNNK; t++) nb[((size_t)b * N1 + i) * KNNK + t] = bi_[t];

    const float* vb = v + (size_t)b * N1 * 3;
    float sdx[KNNK], sdy[KNNK], sdz[KNNK];
#pragma unroll
    for (int k = 0; k < KNNK; k++) {
        int j = bi_[k];
        float dx = vb[j * 3] - vb[i * 3];
        float dy = vb[j * 3 + 1] - vb[i * 3 + 1];
        float dz = vb[j * 3 + 2] - vb[i * 3 + 2];
        float nm = fmaxf(sqrtf(dx * dx + dy * dy + dz * dz), 1e-12f);
        sdx[k] = dx / nm; sdy[k] = dy / nm; sdz[k] = dz / nm;
    }
    float* fmrow = fm + ((size_t)b * N1 + i) * 32;
    for (int f = 0; f < 32; f++) {
        float d0v = sd0[f * 3], d1v = sd0[f * 3 + 1], d2v = sd0[f * 3 + 2];
        float m = 0.f;
#pragma unroll
        for (int k = 0; k < KNNK; k++) {
            float th = fmaxf(sdx[k] * d0v + sdy[k] * d1v + sdz[k] * d2v, 0.f);
            m = fmaxf(m, th);
        }
        fmrow[f] = m;
    }
}

// ======================= coord gather (pool selection of xyz rows) =======================
__global__ void gather_coords_kernel(const float* __restrict__ vin, const int* __restrict__ pool,
                                     float* __restrict__ vout, int Nin, int Nout) {
    int idx = blockIdx.x * blockDim.x + threadIdx.x;
    if (idx >= BATCH * Nout * 3) return;
    int f = idx % 3; int r = idx / 3; int b = r / Nout; int pp = r % Nout;
    vout[idx] = vin[((size_t)b * Nin + pool[pp]) * 3 + f];
}

// ======================= conv_layer activation: float4 channels per thread ==============
__global__ void conv_act_kernel(const float* __restrict__ v, const int* __restrict__ nb,
                                const float* __restrict__ ndirs, const float* __restrict__ fo,
                                float* __restrict__ out, int N, int OC, int G, int relu_out) {
    int C = 2 * OC;
    __shared__ float sdx[320], sdy[320], sdz[320];
    __shared__ int sj[320];
    int p0 = blockIdx.x * G;
    int t = threadIdx.x;
    for (int e = t; e < G * KNNK; e += 256) {
        int g = e / KNNK, k = e % KNNK;
        int p = p0 + g; int b = p / N; int n = p % N;
        const float* vb = v + (size_t)b * N * 3;
        int j = nb[(size_t)p * KNNK + k];
        sj[e] = b * N + j;
        float dx = vb[j * 3] - vb[n * 3];
        float dy = vb[j * 3 + 1] - vb[n * 3 + 1];
        float dz = vb[j * 3 + 2] - vb[n * 3 + 2];
        float nm = fmaxf(sqrtf(dx * dx + dy * dy + dz * dz), 1e-12f);
        sdx[e] = dx / nm; sdy[e] = dy / nm; sdz[e] = dz / nm;
    }
    __syncthreads();
    int TP = 256 / G;
    int g = t / TP, fq = t % TP;
    int p = p0 + g;
    int kb = g * KNNK;
    int OCq = OC / 4;
    const float* forow = fo + (size_t)p * C;
    for (int f4 = fq; f4 < OCq; f4 += TP) {
        int f = f4 * 4;
        float4 dA = *(const float4*)&ndirs[f * 3];
        float4 dB = *(const float4*)&ndirs[f * 3 + 4];
        float4 dC = *(const float4*)&ndirs[f * 3 + 8];
        float m0 = -INFINITY, m1 = -INFINITY, m2 = -INFINITY, m3 = -INFINITY;
#pragma unroll
        for (int k = 0; k < KNNK; k++) {
            float sx = sdx[kb + k], sy = sdy[kb + k], sz = sdz[kb + k];
            float4 fs = *(const float4*)&fo[(size_t)sj[kb + k] * C + OC + f];
            float th0 = fmaxf(sx * dA.x + sy * dA.y + sz * dA.z, 0.f);
            float th1 = fmaxf(sx * dA.w + sy * dB.x + sz * dB.y, 0.f);
            float th2 = fmaxf(sx * dB.z + sy * dB.w + sz * dC.x, 0.f);
            float th3 = fmaxf(sx * dC.y + sy * dC.z + sz * dC.w, 0.f);
            m0 = fmaxf(m0, th0 * fs.x);
            m1 = fmaxf(m1, th1 * fs.y);
            m2 = fmaxf(m2, th2 * fs.z);
            m3 = fmaxf(m3, th3 * fs.w);
        }
        float4 fr = *(const float4*)&forow[f];
        float4 val = make_float4(fr.x + m0, fr.y + m1, fr.z + m2, fr.w + m3);
        if (relu_out) {
            val.x = fmaxf(val.x, 0.f); val.y = fmaxf(val.y, 0.f);
            val.z = fmaxf(val.z, 0.f); val.w = fmaxf(val.w, 0.f);
        }
        *(float4*)&out[(size_t)p * OC + f] = val;
    }
}

// ======================= gather_max + pool (features only) =======================
__global__ void gather_max_pool_kernel(const float* __restrict__ fm, const int* __restrict__ nb,
                                       const int* __restrict__ pool, float* __restrict__ out,
                                       int Nin, int Nout, int F) {
    int F4 = F / 4;
    int idx = blockIdx.x * blockDim.x + threadIdx.x;
    int tot = BATCH * Nout * F4;
    if (idx >= tot) return;
    int f4 = idx % F4; int r = idx / F4; int b = r / Nout; int pp = r % Nout;
    int row = pool[pp];
    const int* nbp = nb + ((size_t)b * Nin + row) * KNNK;
    float4 m = make_float4(-INFINITY, -INFINITY, -INFINITY, -INFINITY);
#pragma unroll
    for (int k = 0; k < KNNK; k++) {
        const float4 vv = *(const float4*)&fm[((size_t)b * Nin + nbp[k]) * F + f4 * 4];
        m.x = fmaxf(m.x, vv.x); m.y = fmaxf(m.y, vv.y);
        m.z = fmaxf(m.z, vv.z); m.w = fmaxf(m.w, vv.w);
    }
    *(float4*)&out[(size_t)r * F + f4 * 4] = m;
}

// ======================= 128x128 SGEMM (R12 winner form) =======================
#define GT 132
__global__ __launch_bounds__(256, 2) void gemm128_kernel(
        const float* __restrict__ A, const float* __restrict__ B,
        const float* __restrict__ bias, float* __restrict__ C,
        int M, int K, int N) {
    __shared__ float As[8][GT];
    __shared__ float Bs[8][GT];
    int row0 = blockIdx.y * 128, col0 = blockIdx.x * 128;
    int tid = threadIdx.x;
    int tx = tid % 16, ty = tid / 16;
    int arow = tid >> 1, acol = (tid & 1) * 4;
    int brow = tid >> 5, bcol = (tid & 31) * 4;
    float4 pa = *(const float4*)&A[(size_t)(row0 + arow) * K + acol];
    float4 pb = *(const float4*)&B[(size_t)brow * N + col0 + bcol];
    float acc[8][8] = {};
    for (int k0 = 0; k0 < K; k0 += 8) {
        As[acol][arow] = pa.x; As[acol + 1][arow] = pa.y;
        As[acol + 2][arow] = pa.z; As[acol + 3][arow] = pa.w;
        *(float4*)&Bs[brow][bcol] = pb;
        __syncthreads();
        if (k0 + 8 < K) {
            pa = *(const float4*)&A[(size_t)(row0 + arow) * K + k0 + 8 + acol];
            pb = *(const float4*)&B[(size_t)(k0 + 8 + brow) * N + col0 + bcol];
        }
#pragma unroll
        for (int kk = 0; kk < 8; kk++) {
            float a[8], bb[8];
            *(float4*)&a[0] = *(const float4*)&As[kk][ty * 8];
            *(float4*)&a[4] = *(const float4*)&As[kk][ty * 8 + 4];
            *(float4*)&bb[0] = *(const float4*)&Bs[kk][tx * 8];
            *(float4*)&bb[4] = *(const float4*)&Bs[kk][tx * 8 + 4];
#pragma unroll
            for (int i = 0; i < 8; i++)
#pragma unroll
                for (int j = 0; j < 8; j++) acc[i][j] = fmaf(a[i], bb[j], acc[i][j]);
        }
        __syncthreads();
    }
    float bz[8];
    if (bias) {
        *(float4*)&bz[0] = *(const float4*)&bias[col0 + tx * 8];
        *(float4*)&bz[4] = *(const float4*)&bias[col0 + tx * 8 + 4];
    } else {
#pragma unroll
        for (int j = 0; j < 8; j++) bz[j] = 0.f;
    }
#pragma unroll
    for (int i = 0; i < 8; i++) {
        float* crow = &C[(size_t)(row0 + ty * 8 + i) * N + col0 + tx * 8];
        float4 r0 = make_float4(acc[i][0] + bz[0], acc[i][1] + bz[1], acc[i][2] + bz[2], acc[i][3] + bz[3]);
        float4 r1 = make_float4(acc[i][4] + bz[4], acc[i][5] + bz[5], acc[i][6] + bz[6], acc[i][7] + bz[7]);
        *(float4*)crow = r0;
        *(float4*)(crow + 4) = r1;
    }
}

// ======================= cluster GEMM: 32x64 tiles, tile-compensated =======================
__global__ void gemm_kahan_kernel(const float* __restrict__ A, const float* __restrict__ B,
                                  float* __restrict__ C, int M, int K, int N) {
    __shared__ float As[16][36];
    __shared__ float Bs[16][68];
    int row0 = blockIdx.y * 32;
    int tid = threadIdx.x;
    int tx = tid % 16, ty = tid / 16;
    float acc[2][4] = {}; float cmp[2][4] = {};
    int ar = tid >> 2, ac4 = (tid & 3) * 4;
    int br = tid >> 4, bc4 = (tid & 15) * 4;
    for (int k0 = 0; k0 < K; k0 += 16) {
        if (tid < 128) {
            float4 av = *(const float4*)&A[(size_t)(row0 + ar) * K + k0 + ac4];
            As[ac4][ar] = av.x; As[ac4 + 1][ar] = av.y; As[ac4 + 2][ar] = av.z; As[ac4 + 3][ar] = av.w;
        }
        *(float4*)&Bs[br][bc4] = *(const float4*)&B[(size_t)(k0 + br) * N + bc4];
        __syncthreads();
        float tacc[2][4] = {};
#pragma unroll
        for (int kk = 0; kk < 16; kk++) {
            float a[2], bb[4];
            a[0] = As[kk][ty * 2]; a[1] = As[kk][ty * 2 + 1];
            float4 b4 = *(const float4*)&Bs[kk][tx * 4];
            bb[0] = b4.x; bb[1] = b4.y; bb[2] = b4.z; bb[3] = b4.w;
#pragma unroll
            for (int i = 0; i < 2; i++)
#pragma unroll
                for (int j = 0; j < 4; j++) tacc[i][j] = fmaf(a[i], bb[j], tacc[i][j]);
        }
#pragma unroll
        for (int i = 0; i < 2; i++)
#pragma unroll
            for (int j = 0; j < 4; j++) kadd(acc[i][j], cmp[i][j], tacc[i][j]);
        __syncthreads();
    }
#pragma unroll
    for (int i = 0; i < 2; i++)
#pragma unroll
        for (int j = 0; j < 4; j++)
            C[(size_t)(row0 + ty * 2 + i) * N + tx * 4 + j] = acc[i][j];
}

// ======================= GeM =======================
__device__ __forceinline__ float fast_pow(float x, float p) {
    return exp2f(p * log2f(x));
}
__global__ void gem_kernel(const float* __restrict__ fm4, const float* __restrict__ gem_p,
                           float* __restrict__ y) {
    int b = blockIdx.x;
    int c4 = threadIdx.x * 4;
    float p = gem_p[0];
    bool p3 = (p == 3.0f);
    float s[4] = {}; float sc[4] = {};
    for (int nc = 0; nc < 8; nc++) {
        float t[4] = {};
        for (int n = nc * 32; n < nc * 32 + 32; n++) {
            float4 f = *(const float4*)&fm4[((size_t)b * N3 + n) * 1024 + c4];
            float fx = fmaxf(f.x, 1e-6f), fy = fmaxf(f.y, 1e-6f);
            float fz = fmaxf(f.z, 1e-6f), fw = fmaxf(f.w, 1e-6f);
            if (p3) {
                t[0] = __fadd_rn(t[0], fx * fx * fx);
                t[1] = __fadd_rn(t[1], fy * fy * fy);
                t[2] = __fadd_rn(t[2], fz * fz * fz);
                t[3] = __fadd_rn(t[3], fw * fw * fw);
            } else {
                t[0] = __fadd_rn(t[0], fast_pow(fx, p));
                t[1] = __fadd_rn(t[1], fast_pow(fy, p));
                t[2] = __fadd_rn(t[2], fast_pow(fz, p));
                t[3] = __fadd_rn(t[3], fast_pow(fw, p));
            }
        }
#pragma unroll
        for (int u = 0; u < 4; u++) kadd(s[u], sc[u], t[u]);
    }
    float4 r;
    if (p3) {
        r.x = cbrtf(s[0] / (float)N3); r.y = cbrtf(s[1] / (float)N3);
        r.z = cbrtf(s[2] / (float)N3); r.w = cbrtf(s[3] / (float)N3);
    } else {
        float ip = 1.f / p;
        r.x = fast_pow(s[0] / (float)N3, ip); r.y = fast_pow(s[1] / (float)N3, ip);
        r.z = fast_pow(s[2] / (float)N3, ip); r.w = fast_pow(s[3] / (float)N3, ip);
    }
    *(float4*)&y[b * 1024 + c4] = r;
}

// ======================= NetVLAD =======================
__global__ void bn1_stats_kernel(const float* __restrict__ act, float* __restrict__ mean,
                                 float* __restrict__ var, int rows) {
    int k = blockIdx.x;
    __shared__ double sd[256];
    float a = 0.f, ac = 0.f;
    for (int r = threadIdx.x; r < rows; r += 256) kadd(a, ac, act[(size_t)r * 64 + k]);
    sd[threadIdx.x] = (double)a; __syncthreads();
    for (int s = 128; s > 0; s >>= 1) {
        if (threadIdx.x < s) sd[threadIdx.x] += sd[threadIdx.x + s];
        __syncthreads();
    }
    float m = (float)(sd[0] / rows);
    __syncthreads();
    float q = 0.f, qc = 0.f;
    for (int r = threadIdx.x; r < rows; r += 256) {
        float d = __fadd_rn(act[(size_t)r * 64 + k], -m);
        kadd(q, qc, __fmul_rn(d, d));
    }
    sd[threadIdx.x] = (double)q; __syncthreads();
    for (int s = 128; s > 0; s >>= 1) {
        if (threadIdx.x < s) sd[threadIdx.x] += sd[threadIdx.x + s];
        __syncthreads();
    }
    if (threadIdx.x == 0) { mean[k] = m; var[k] = (float)(sd[0] / rows); }
}

__global__ void bn_softmax_kernel(float* __restrict__ act, const float* __restrict__ mean,
                                  const float* __restrict__ var, const float* __restrict__ g,
                                  const float* __restrict__ bb) {
    int r = blockIdx.x * 4 + threadIdx.x / 64;
    int k = threadIdx.x % 64;
    int rb = (threadIdx.x / 64) * 64;
    __shared__ float sv[256];
    float v = (act[(size_t)r * 64 + k] - mean[k]) * rsqrtf(var[k] + 1e-5f) * g[k] + bb[k];
    sv[threadIdx.x] = v; __syncthreads();
    float mx = -INFINITY;
    for (int t = 0; t < 64; t++) mx = fmaxf(mx, sv[rb + t]);
    float e = expf(v - mx);
    __syncthreads(); sv[threadIdx.x] = e; __syncthreads();
    float s = 0.f, sc = 0.f;
    for (int t = 0; t < 64; t++) kadd(s, sc, sv[rb + t]);
    act[(size_t)r * 64 + k] = e / s;
}

// vlad with asum computed in-block
__global__ void vlad_kernel(const float* __restrict__ act, const float* __restrict__ xv,
                            const float* __restrict__ cw2, float* __restrict__ vlad) {
    int b = blockIdx.y;
    int k = threadIdx.x % 64;
    int fi = threadIdx.x / 64;
    int f = blockIdx.x * 4 + fi;
    __shared__ float sasum[64];
    float s = 0.f, sc = 0.f;
    for (int m0 = 0; m0 < N3; m0 += 32) {
        float bs = 0.f;
#pragma unroll 8
        for (int m = m0; m < m0 + 32; m++) {
            bs = fmaf(act[((size_t)b * N3 + m) * 64 + k], xv[((size_t)b * N3 + m) * 1024 + f], bs);
        }
        kadd(s, sc, bs);
    }
    if (fi == 0) {
        float sa = 0.f, sac = 0.f;
        for (int m0 = 0; m0 < N3; m0 += 32) {
            float bsa = 0.f;
#pragma unroll 8
            for (int m = m0; m < m0 + 32; m++) bsa = __fadd_rn(bsa, act[((size_t)b * N3 + m) * 64 + k]);
            kadd(sa, sac, bsa);
        }
        sasum[k] = sa;
    }
    __syncthreads();
    s = __fadd_rn(s, -__fmul_rn(sasum[k], cw2[(size_t)f * 64 + k]));
    vlad[((size_t)b * 1024 + f) * 64 + k] = s;
}

// colnorm + tn fused
__global__ void colnorm_tn_kernel(const float* __restrict__ vlad, float* __restrict__ cn,
                                  float* __restrict__ tn) {
    int b = blockIdx.x; int tid = threadIdx.x;
    int k = tid % 64, grp = tid / 64;
    float s = 0.f, sc = 0.f;
    for (int q0 = 0; q0 < 64; q0 += 16) {
        float bs = 0.f;
#pragma unroll
        for (int q = q0; q < q0 + 16; q++) {
            int f = grp + q * 16;
            float v = vlad[((size_t)b * 1024 + f) * 64 + k];
            bs = fmaf(v, v, bs);
        }
        kadd(s, sc, bs);
    }
    __shared__ double sm[1024];
    __shared__ float scn[64];
    sm[tid] = (double)s; __syncthreads();
    if (grp == 0) {
        double t = 0.0;
        for (int g2 = 0; g2 < 16; g2++) t += sm[g2 * 64 + k];
        float cv = (float)t;
        cn[b * 64 + k] = cv;
        scn[k] = cv;
    }
    __syncthreads();
    if (tid == 0) {
        double t = 0.0;
        for (int k2 = 0; k2 < 64; k2++) {
            float c = scn[k2];
            float d = fmaxf(sqrtf(c), 1e-12f);
            t += (double)(c / (d * d));
        }
        tn[b] = (float)t;
    }
}

// hidden skinny GEMM with fused vlad normalization on smem load
#define SKC 1024
__global__ void skinny8_norm_kernel(const float* __restrict__ A, const float* __restrict__ W,
                                    const float* __restrict__ cn, const float* __restrict__ tn,
                                    float* __restrict__ part, int K, int N) {
    int j = blockIdx.x * 256 + threadIdx.x;
    int k0 = blockIdx.y * SKC;
    __shared__ float xs[BATCH * SKC];
    __shared__ float s1[BATCH * 64];
    __shared__ float s2[BATCH];
    if (threadIdx.x < 8) s2[threadIdx.x] = 1.f / fmaxf(sqrtf(tn[threadIdx.x]), 1e-12f);
    for (int t = threadIdx.x; t < BATCH * 64; t += 256)
        s1[t] = 1.f / fmaxf(sqrtf(cn[t]), 1e-12f);
    __syncthreads();
    for (int t = threadIdx.x; t < BATCH * SKC; t += 256) {
        int bb = t / SKC; int ii = t % SKC;
        int gi = k0 + ii; int k = gi & 63;
        xs[t] = A[(size_t)bb * K + gi] * s1[bb * 64 + k] * s2[bb];
    }
    __syncthreads();
    if (j < N) {
        float acc[BATCH] = {}; float cmp[BATCH] = {};
#pragma unroll 1
        for (int i0 = 0; i0 < SKC; i0 += 16) {
            float ba[BATCH] = {};
#pragma unroll 8
            for (int i = i0; i < i0 + 16; i++) {
                float w = W[(size_t)(k0 + i) * N + j];
#pragma unroll
                for (int bb = 0; bb < BATCH; bb++) ba[bb] = fmaf(xs[bb * SKC + i], w, ba[bb]);
            }
#pragma unroll
            for (int bb = 0; bb < BATCH; bb++) kadd(acc[bb], cmp[bb], ba[bb]);
        }
#pragma unroll
        for (int bb = 0; bb < BATCH; bb++) {
            part[(size_t)blockIdx.y * BATCH * N + bb * N + j] = acc[bb];
        }
    }
}

// gating skinny GEMM with fused bn2-from-partials + gate BN + sigmoid + multiply
__global__ void skinny8_gate_kernel(const float* __restrict__ part,
                                    const float* __restrict__ bn2_g, const float* __restrict__ bn2_b,
                                    const float* __restrict__ W,
                                    const float* __restrict__ gg, const float* __restrict__ gb,
                                    float* __restrict__ desc) {
    int j = blockIdx.x * 256 + threadIdx.x;
    __shared__ float xs[BATCH * 1024];
    for (int i = 0; i < 4; i++) {
        int jj = threadIdx.x + i * 256;
        float h[BATCH];
#pragma unroll
        for (int b = 0; b < BATCH; b++) {
            float s = 0.f, sc = 0.f;
            for (int c = 0; c < 64; c++) kadd(s, sc, part[(size_t)c * BATCH * 1024 + b * 1024 + jj]);
            h[b] = s;
        }
        double m = 0.0;
#pragma unroll
        for (int b = 0; b < BATCH; b++) m += (double)h[b];
        m /= BATCH;
        double q = 0.0;
#pragma unroll
        for (int b = 0; b < BATCH; b++) { double d = (double)h[b] - m; q += d * d; }
        q /= BATCH;
        float mf = (float)m;
        float inv = rsqrtf((float)q + 1e-5f);
#pragma unroll
        for (int b = 0; b < BATCH; b++)
            xs[b * 1024 + jj] = (h[b] - mf) * inv * bn2_g[jj] + bn2_b[jj];
    }
    __syncthreads();
    float acc[BATCH] = {}; float cmp[BATCH] = {};
#pragma unroll 1
    for (int i0 = 0; i0 < 1024; i0 += 16) {
        float ba[BATCH] = {};
#pragma unroll 4
        for (int i = i0; i < i0 + 16; i++) {
            float w = W[(size_t)i * 1024 + j];
#pragma unroll
            for (int bb = 0; bb < BATCH; bb++) ba[bb] = fmaf(xs[bb * 1024 + i], w, ba[bb]);
        }
#pragma unroll
        for (int bb = 0; bb < BATCH; bb++) kadd(acc[bb], cmp[bb], ba[bb]);
    }
    double m = 0.0;
#pragma unroll
    for (int bb = 0; bb < BATCH; bb++) m += (double)acc[bb];
    m /= BATCH;
    double q = 0.0;
#pragma unroll
    for (int bb = 0; bb < BATCH; bb++) { double d = (double)acc[bb] - m; q += d * d; }
    q /= BATCH;
    float mf = (float)m;
    float inv = rsqrtf((float)q + 1e-5f);
#pragma unroll
    for (int bb = 0; bb < BATCH; bb++) {
        float z = (acc[bb] - mf) * inv * gg[j] + gb[j];
        float s = 1.f / (1.f + expf(-z));
        desc[bb * 1024 + j] = xs[bb * 1024 + j] * s;
    }
}

// ======================= host: numpy-compatible MT19937 pools =======================
struct MTState { uint32_t mt[624]; int idx; };

static void mt_seed(MTState& s, uint32_t seed) {
    for (int p = 0; p < 624; p++) {
        s.mt[p] = seed;
        seed = 1812433253u * (seed ^ (seed >> 30)) + (uint32_t)p + 1u;
    }
    s.idx = 624;
}
static uint32_t mt_next(MTState& s) {
    if (s.idx >= 624) {
        for (int i = 0; i < 624; i++) {
            uint32_t y = (s.mt[i] & 0x80000000u) | (s.mt[(i + 1) % 624] & 0x7fffffffu);
            uint32_t v = s.mt[(i + 397) % 624] ^ (y >> 1);
            if (y & 1u) v ^= 0x9908b0dfu;
            s.mt[i] = v;
        }
        s.idx = 0;
    }
    uint32_t y = s.mt[s.idx++];
    y ^= y >> 11;
    y ^= (y << 7) & 0x9d2c5680u;
    y ^= (y << 15) & 0xefc60000u;
    y ^= y >> 18;
    return y;
}
static uint32_t rk_interval(MTState& s, uint32_t mx) {
    if (mx == 0) return 0;
    uint32_t mask = mx;
    mask |= mask >> 1; mask |= mask >> 2; mask |= mask >> 4;
    mask |= mask >> 8; mask |= mask >> 16;
    uint32_t v;
    while ((v = (mt_next(s) & mask)) > mx) {}
    return v;
}
static void np_permutation(uint32_t seed, int n, int* out) {
    for (int i = 0; i < n; i++) out[i] = i;
    MTState s; mt_seed(s, seed);
    for (int i = n - 1; i >= 1; i--) {
        uint32_t j = rk_interval(s, (uint32_t)i);
        int t = out[i]; out[i] = out[(int)j]; out[(int)j] = t;
    }
}

// ======================= launch (deep fork/join graph parallelism) =======================
extern "C" void kernel_launch(void* const* d_in, const int* in_sizes, int n_in,
                              void* d_out, int out_size) {
    const float* x         = (const float*)d_in[0];
    const float* dir0      = (const float*)d_in[1];
    const float* W1        = (const float*)d_in[2];
    const float* b1        = (const float*)d_in[3];
    const float* dir1      = (const float*)d_in[4];
    const float* W2        = (const float*)d_in[5];
    const float* b2        = (const float*)d_in[6];
    const float* dir2      = (const float*)d_in[7];
    const float* W3        = (const float*)d_in[8];
    const float* b3        = (const float*)d_in[9];
    const float* dir3      = (const float*)d_in[10];
    const float* W4        = (const float*)d_in[11];
    const float* b4        = (const float*)d_in[12];
    const float* dir4      = (const float*)d_in[13];
    const float* gem_p     = (const float*)d_in[14];
    const float* cluster_w = (const float*)d_in[15];
    const float* cluster_w2= (const float*)d_in[16];
    const float* hidden_w  = (const float*)d_in[17];
    const float* bn1_g     = (const float*)d_in[18];
    const float* bn1_b     = (const float*)d_in[19];
    const float* bn2_g     = (const float*)d_in[20];
    const float* bn2_b     = (const float*)d_in[21];
    const float* gating_w  = (const float*)d_in[22];
    const float* gbn_g     = (const float*)d_in[23];
    const float* gbn_b     = (const float*)d_in[24];
    float* out = (float*)d_out;

    float *fo, *fa, *fb, *ndirs, *v2, *v3, *act, *bnm, *bnv, *vlad, *cn, *tn, *part;
    int *nb1, *nb2, *nb3, *pool1, *pool2;
    cudaGetSymbolAddress((void**)&fo, g_fo);
    cudaGetSymbolAddress((void**)&fa, g_fa);
    cudaGetSymbolAddress((void**)&fb, g_fb);
    cudaGetSymbolAddress((void**)&nb1, g_nb1);
    cudaGetSymbolAddress((void**)&nb2, g_nb2);
    cudaGetSymbolAddress((void**)&nb3, g_nb3);
    cudaGetSymbolAddress((void**)&ndirs, g_ndirs);
    cudaGetSymbolAddress((void**)&pool1, g_pool1);
    cudaGetSymbolAddress((void**)&pool2, g_pool2);
    cudaGetSymbolAddress((void**)&v2, g_v2);
    cudaGetSymbolAddress((void**)&v3, g_v3);
    cudaGetSymbolAddress((void**)&act, g_act);
    cudaGetSymbolAddress((void**)&bnm, g_bnm);
    cudaGetSymbolAddress((void**)&bnv, g_bnv);
    cudaGetSymbolAddress((void**)&vlad, g_vlad);
    cudaGetSymbolAddress((void**)&cn, g_cn);
    cudaGetSymbolAddress((void**)&tn, g_tn);
    cudaGetSymbolAddress((void**)&part, g_part);

    static PoolParams pp;
    {
        static int perm1[N1];
        static int perm2[N2];
        np_permutation(1u, N1, perm1);
        np_permutation(2u, N2, perm2);
        for (int i = 0; i < 1024; i++) pp.p1[i] = perm1[i];
        for (int i = 0; i < 256;  i++) pp.p2[i] = perm2[i];
    }

    static cudaStream_t sside = nullptr;
    static cudaEvent_t ev[6];
    if (sside == nullptr) {
        cudaStreamCreateWithFlags(&sside, cudaStreamNonBlocking);
        for (int i = 0; i < 6; i++) cudaEventCreateWithFlags(&ev[i], cudaEventDisableTiming);
    }

    const float* nd1 = ndirs + 32 * 3;
    const float* nd2 = ndirs + 96 * 3;
    const float* nd3 = ndirs + 224 * 3;
    const float* nd4 = ndirs + 480 * 3;

    // ================= stage 1 =================
    knn_init_surf_kernel<<<dim3(N1 / 128, BATCH), 128>>>(pp, dir0, dir1, dir2, dir3, dir4, x, nb1, fa);

    // fork after init: side stream computes v2, knn2, v3, knn3 (pools + x only)
    cudaEventRecord(ev[0], 0);
    cudaStreamWaitEvent(sside, ev[0], 0);
    gather_coords_kernel<<<(BATCH * N2 * 3 + 255) / 256, 256, 0, sside>>>(x, pool1, v2, N1, N2);
    knn_kernel<<<dim3(N2 / 128, BATCH), 128, 0, sside>>>(v2, N2, nb2);
    cudaEventRecord(ev[1], sside);
    gather_coords_kernel<<<(BATCH * N3 * 3 + 255) / 256, 256, 0, sside>>>(v2, pool2, v3, N2, N3);
    knn_kernel<<<dim3(N3 / 128, BATCH), 128, 0, sside>>>(v3, N3, nb3);
    cudaEventRecord(ev[2], sside);

    // main: stage-1 feature chain
    gemm128_kernel<<<dim3(1, BATCH * N1 / 128), 256>>>(fa, W1, b1, fo, BATCH * N1, 32, 128);
    conv_act_kernel<<<BATCH * N1 / 16, 256>>>(x, nb1, nd1, fo, fb, N1, 64, 16, 1);
    gather_max_pool_kernel<<<(BATCH * N2 * 16 + 255) / 256, 256>>>(fb, nb1, pool1, fa, N1, N2, 64);

    // ================= stage 2 =================
    gemm128_kernel<<<dim3(2, BATCH * N2 / 128), 256>>>(fa, W2, b2, fo, BATCH * N2, 64, 256);
    cudaStreamWaitEvent(0, ev[1], 0);   // need nb2 + v2
    conv_act_kernel<<<BATCH * N2 / 8, 256>>>(v2, nb2, nd2, fo, fb, N2, 128, 8, 1);
    gemm128_kernel<<<dim3(4, BATCH * N2 / 128), 256>>>(fb, W3, b3, fo, BATCH * N2, 128, 512);
    conv_act_kernel<<<BATCH * N2 / 4, 256>>>(v2, nb2, nd3, fo, fa, N2, 256, 4, 1);
    gather_max_pool_kernel<<<(BATCH * N3 * 64 + 255) / 256, 256>>>(fa, nb2, pool2, fb, N2, N3, 256);

    // ================= stage 3 =================
    gemm128_kernel<<<dim3(16, BATCH * N3 / 128), 256>>>(fb, W4, b4, fo, BATCH * N3, 256, 2048);
    cudaStreamWaitEvent(0, ev[2], 0);   // need nb3 + v3
    conv_act_kernel<<<BATCH * N3, 256>>>(v3, nb3, nd4, fo, fa, N3, 1024, 1, 0);

    // fork: GeM (y) ∥ NetVLAD tail (both read fa only)
    cudaEventRecord(ev[3], 0);
    cudaStreamWaitEvent(sside, ev[3], 0);
    gem_kernel<<<BATCH, 256, 0, sside>>>(fa, gem_p, out);
    cudaEventRecord(ev[4], sside);

    // ================= NetVLAD =================
    gemm_kahan_kernel<<<dim3(1, BATCH * N3 / 32), 256>>>(fa, cluster_w, act, BATCH * N3, 1024, 64);
    bn1_stats_kernel<<<64, 256>>>(act, bnm, bnv, BATCH * N3);
    bn_softmax_kernel<<<BATCH * N3 / 4, 256>>>(act, bnm, bnv, bn1_g, bn1_b);
    vlad_kernel<<<dim3(256, BATCH), 256>>>(act, fa, cluster_w2, vlad);
    colnorm_tn_kernel<<<BATCH, 1024>>>(vlad, cn, tn);
    skinny8_norm_kernel<<<dim3(4, 64), 256>>>(vlad, hidden_w, cn, tn, part, 65536, 1024);
    skinny8_gate_kernel<<<4, 256>>>(part, bn2_g, bn2_b, gating_w, gbn_g, gbn_b, out + BATCH * 1024);

    cudaStreamWaitEvent(0, ev[4], 0);
}